// round 2
// baseline (speedup 1.0000x reference)
#include <cuda_runtime.h>
#include <cuda_bf16.h>
#include <math.h>

// ---------------- problem constants ----------------
#define BB     32
#define SS     1024
#define MAXL   500
#define EMB    768
#define HH     100
#define DD     200           // 2*H
#define KLAY   3
#define NTOK   (BB*MAXL)     // 16000

// ---------------- scratch buffer (static device global; no allocation) ----------------
// offsets in floats
#define O_TMPS  0LL
#define O_XPF   (O_TMPS + (long long)NTOK*EMB)          // 12,288,000
#define O_XPB   (O_XPF  + (long long)NTOK*4*HH)         // +6,400,000
#define O_X     (O_XPB  + (long long)NTOK*4*HH)
#define O_HOUT  (O_X    + (long long)NTOK*DD)
#define O_OUTS  (O_HOUT + (long long)BB*DD)
#define O_OUTG  (O_OUTS + (long long)NTOK*DD)
#define O_QKV   (O_OUTG + (long long)NTOK*DD)
#define O_SC    (O_QKV  + (long long)NTOK*3*DD)
#define O_CTX   (O_SC   + (long long)BB*MAXL*MAXL)
#define O_P1    (O_CTX  + (long long)NTOK*DD)
#define O_A     (O_P1   + (long long)NTOK*DD)
#define O_H     (O_A    + (long long)NTOK*DD)
#define O_ADJ   (O_H    + (long long)NTOK*DD)
#define O_DEN   (O_ADJ  + (long long)BB*MAXL*MAXL)
#define O_Y     (O_DEN  + (long long)NTOK)
#define O_Z     (O_Y    + (long long)NTOK*DD)
#define O_TOTAL (O_Z    + (long long)NTOK*DD)

__device__ float d_buf[O_TOTAL];

// ---------------- kernel: tmps = segment-sum of bert_out[:,1:,:] ----------------
__global__ void tmps_kernel(const float* __restrict__ bert, const int* __restrict__ tran_idx,
                            float* __restrict__ tmps)
{
    long long bl = blockIdx.x;                 // 0..15999
    int b = (int)(bl / MAXL);
    int s = tran_idx[bl*2 + 0];
    int e = tran_idx[bl*2 + 1];
    for (int c = threadIdx.x; c < EMB; c += blockDim.x) {
        float acc = 0.f;
        for (int t = s; t < e; t++) {
            acc += bert[((long long)b*SS + (t+1))*EMB + c];
        }
        tmps[bl*EMB + c] = acc;
    }
}

// ---------------- generic tiled fp32 GEMM (NN / NT, strided-batched, optional bias) ----------------
// C[bz](M,N) = alpha * A[bz](M,K) @ (transB? B[bz]^T : B[bz]) + bias
#define BM 64
#define BN 64
#define BKT 16
__global__ __launch_bounds__(256)
void sgemm_kernel(const float* __restrict__ A, int lda, long long sA,
                  const float* __restrict__ Bm, int ldb, long long sB,
                  const float* __restrict__ bias,
                  float* __restrict__ C, int ldc, long long sC,
                  int M, int N, int Kd, float alpha, int transB)
{
    int bz = blockIdx.z;
    A  += (long long)bz * sA;
    Bm += (long long)bz * sB;
    C  += (long long)bz * sC;

    __shared__ float As[BKT][BM];
    __shared__ float Bs[BKT][BN + 4];

    int tid = threadIdx.x;
    int tx = tid & 15;          // 0..15 -> N
    int ty = tid >> 4;          // 0..15 -> M
    int row0 = blockIdx.x * BM;
    int col0 = blockIdx.y * BN;

    float acc[4][4];
#pragma unroll
    for (int i = 0; i < 4; i++)
#pragma unroll
        for (int j = 0; j < 4; j++) acc[i][j] = 0.f;

    for (int k0 = 0; k0 < Kd; k0 += BKT) {
        // load A tile (BM x BKT)
        {
            int r  = tid >> 2;
            int kk = (tid & 3) * 4;
            int grow = row0 + r;
#pragma unroll
            for (int i = 0; i < 4; i++) {
                int gk = k0 + kk + i;
                float v = 0.f;
                if (grow < M && gk < Kd) v = A[(long long)grow*lda + gk];
                As[kk + i][r] = v;
            }
        }
        // load B tile (BKT x BN)
        if (!transB) {
            int kk = tid >> 4;
            int nb = (tid & 15) * 4;
            int gk = k0 + kk;
#pragma unroll
            for (int i = 0; i < 4; i++) {
                int gn = col0 + nb + i;
                float v = 0.f;
                if (gk < Kd && gn < N) v = Bm[(long long)gk*ldb + gn];
                Bs[kk][nb + i] = v;
            }
        } else {
            int n  = tid >> 2;
            int kk = (tid & 3) * 4;
            int gn = col0 + n;
#pragma unroll
            for (int i = 0; i < 4; i++) {
                int gk = k0 + kk + i;
                float v = 0.f;
                if (gn < N && gk < Kd) v = Bm[(long long)gn*ldb + gk];
                Bs[kk + i][n] = v;
            }
        }
        __syncthreads();

#pragma unroll
        for (int kk = 0; kk < BKT; kk++) {
            float a[4], b[4];
#pragma unroll
            for (int i = 0; i < 4; i++) a[i] = As[kk][ty*4 + i];
#pragma unroll
            for (int j = 0; j < 4; j++) b[j] = Bs[kk][tx*4 + j];
#pragma unroll
            for (int i = 0; i < 4; i++)
#pragma unroll
                for (int j = 0; j < 4; j++)
                    acc[i][j] += a[i] * b[j];
        }
        __syncthreads();
    }

#pragma unroll
    for (int i = 0; i < 4; i++) {
        int r = row0 + ty*4 + i;
        if (r >= M) continue;
#pragma unroll
        for (int j = 0; j < 4; j++) {
            int c = col0 + tx*4 + j;
            if (c >= N) continue;
            float v = acc[i][j] * alpha;
            if (bias) v += bias[c];
            C[(long long)r*ldc + c] = v;
        }
    }
}

// ---------------- LSTM recurrence: one block per (batch, direction) ----------------
__global__ __launch_bounds__(400, 1)
void lstm_kernel(const float* __restrict__ xpf, const float* __restrict__ xpb,
                 const float* __restrict__ Whh_f, const float* __restrict__ Whh_b,
                 const int* __restrict__ tran_len,
                 float* __restrict__ x, float* __restrict__ hout)
{
    int b   = blockIdx.x >> 1;
    int dir = blockIdx.x & 1;
    const float* xp  = dir ? xpb : xpf;
    const float* Whh = dir ? Whh_b : Whh_f;
    int tl = tran_len[b];
    int j = threadIdx.x;  // 0..399

    float w[HH];
#pragma unroll
    for (int k = 0; k < HH; k++) w[k] = Whh[k*4*HH + j];

    __shared__ float h[HH + 4], c[HH + 4], gates[4*HH];
    if (j < HH + 4) { h[j] = 0.f; c[j] = 0.f; }
    __syncthreads();

    const float* xpb_base = xp + (long long)b * MAXL * 4*HH;

    int pos0 = dir ? (MAXL - 1) : 0;
    float xcur = xpb_base[(long long)pos0*4*HH + j];

    for (int t = 0; t < MAXL; t++) {
        int pos = dir ? (MAXL - 1 - t) : t;
        // prefetch next step's xp
        float xnext = 0.f;
        if (t + 1 < MAXL) {
            int posn = dir ? (MAXL - 2 - t) : (t + 1);
            xnext = xpb_base[(long long)posn*4*HH + j];
        }
        float m = (pos < tl) ? 1.f : 0.f;

        // gate_j = xp + h . Whh[:,j]  (4 independent accumulators)
        float g0 = 0.f, g1 = 0.f, g2 = 0.f, g3 = 0.f;
#pragma unroll
        for (int k = 0; k < HH; k += 4) {
            float4 h4 = *reinterpret_cast<const float4*>(&h[k]);
            g0 += w[k]   * h4.x;
            g1 += w[k+1] * h4.y;
            g2 += w[k+2] * h4.z;
            g3 += w[k+3] * h4.w;
        }
        gates[j] = xcur + ((g0 + g1) + (g2 + g3));
        __syncthreads();

        if (j < HH) {
            float ig = gates[j], fg = gates[j+HH], cg = gates[j+2*HH], og = gates[j+3*HH];
            float si = 1.f / (1.f + __expf(-ig));
            float sf = 1.f / (1.f + __expf(-fg));
            float so = 1.f / (1.f + __expf(-og));
            float cn = sf * c[j] + si * tanhf(cg);
            float hn = so * tanhf(cn);
            float hj = m * hn + (1.f - m) * h[j];
            float cj = m * cn + (1.f - m) * c[j];
            h[j] = hj; c[j] = cj;
            x[((long long)b*MAXL + pos)*DD + dir*HH + j] = hj * m;
        }
        __syncthreads();
        xcur = xnext;
    }
    if (j < HH) hout[b*DD + dir*HH + j] = h[j];
}

// ---------------- elementwise / reduction kernels ----------------
__global__ void adj_kernel(const float* __restrict__ a1, const float* __restrict__ a2,
                           float* __restrict__ adj, long long n)
{
    long long i = (long long)blockIdx.x * blockDim.x + threadIdx.x;
    if (i < n) adj[i] = fminf(a1[i] + a2[i], 1.f);
}

__global__ void denom_kernel(const float* __restrict__ adj, float* __restrict__ den)
{
    long long row = blockIdx.x;
    const float* a = adj + row * MAXL;
    int c = threadIdx.x;                  // 256
    float s = 0.f;
    if (c < MAXL) s = a[c];
    if (c + 256 < MAXL) s += a[c + 256];
    __shared__ float sred[8];
#pragma unroll
    for (int o = 16; o > 0; o >>= 1) s += __shfl_xor_sync(0xffffffffu, s, o);
    if ((c & 31) == 0) sred[c >> 5] = s;
    __syncthreads();
    if (c == 0) {
        float t = 0.f;
#pragma unroll
        for (int w = 0; w < 8; w++) t += sred[w];
        den[row] = t + 1e-7f;
    }
}

__global__ void copy2_kernel(const float* __restrict__ src, float* __restrict__ d1,
                             float* __restrict__ d2, long long n)
{
    long long i = (long long)blockIdx.x * blockDim.x + threadIdx.x;
    if (i < n) { float v = src[i]; d1[i] = v; d2[i] = v; }
}

__global__ void softmax_kernel(float* __restrict__ scores, const int* __restrict__ tran_len)
{
    long long row = blockIdx.x;           // 0..15999
    int b = (int)(row / MAXL);
    int tl = tran_len[b];
    float* s = scores + row * MAXL;
    int c  = threadIdx.x;                 // 256
    int c1 = c + 256;
    float v0 = -1e30f, v1 = -1e30f;
    if (c  < MAXL) v0 = s[c]  + (c  < tl ? 0.f : -10000.f);
    if (c1 < MAXL) v1 = s[c1] + (c1 < tl ? 0.f : -10000.f);
    float m = fmaxf(v0, v1);
    __shared__ float sred[8];
#pragma unroll
    for (int o = 16; o > 0; o >>= 1) m = fmaxf(m, __shfl_xor_sync(0xffffffffu, m, o));
    if ((c & 31) == 0) sred[c >> 5] = m;
    __syncthreads();
    float mm = sred[0];
#pragma unroll
    for (int w = 1; w < 8; w++) mm = fmaxf(mm, sred[w]);
    float e0 = (c  < MAXL) ? __expf(v0 - mm) : 0.f;
    float e1 = (c1 < MAXL) ? __expf(v1 - mm) : 0.f;
    float su = e0 + e1;
#pragma unroll
    for (int o = 16; o > 0; o >>= 1) su += __shfl_xor_sync(0xffffffffu, su, o);
    __syncthreads();
    if ((c & 31) == 0) sred[c >> 5] = su;
    __syncthreads();
    float tot = 0.f;
#pragma unroll
    for (int w = 0; w < 8; w++) tot += sred[w];
    float inv = 1.f / tot;
    if (c  < MAXL) s[c]  = e0 * inv;
    if (c1 < MAXL) s[c1] = e1 * inv;
}

__global__ void ln_residual_kernel(const float* __restrict__ p, const float* __restrict__ res,
                                   const float* __restrict__ g, const float* __restrict__ bb,
                                   float* __restrict__ out)
{
    long long r = blockIdx.x;             // 16000
    int c = threadIdx.x;                  // 256
    float v = 0.f;
    if (c < DD) v = p[r*DD + c] + res[r*DD + c];
    __shared__ float sred[8];
    float s = v;
#pragma unroll
    for (int o = 16; o > 0; o >>= 1) s += __shfl_xor_sync(0xffffffffu, s, o);
    if ((c & 31) == 0) sred[c >> 5] = s;
    __syncthreads();
    float tot = 0.f;
#pragma unroll
    for (int w = 0; w < 8; w++) tot += sred[w];
    float mean = tot * (1.f / DD);
    float dv = (c < DD) ? (v - mean) : 0.f;
    float s2 = dv * dv;
#pragma unroll
    for (int o = 16; o > 0; o >>= 1) s2 += __shfl_xor_sync(0xffffffffu, s2, o);
    __syncthreads();
    if ((c & 31) == 0) sred[c >> 5] = s2;
    __syncthreads();
    float v2 = 0.f;
#pragma unroll
    for (int w = 0; w < 8; w++) v2 += sred[w];
    float var = v2 * (1.f / DD);
    if (c < DD) out[r*DD + c] = dv * rsqrtf(var + 1e-20f) * g[c] + bb[c];
}

__global__ void gelu_kernel(float* __restrict__ h, long long n)
{
    long long i = (long long)blockIdx.x * blockDim.x + threadIdx.x;
    if (i < n) {
        float v = h[i];
        h[i] = 0.5f * v * (1.f + erff(v * 0.70710678118654752f));
    }
}

__global__ void gcn_kernel(const float* __restrict__ z, const float* __restrict__ den,
                           float* __restrict__ outg, long long n)
{
    long long i = (long long)blockIdx.x * blockDim.x + threadIdx.x;
    if (i < n) {
        long long row = i / DD;
        outg[i] += fmaxf(z[i] / den[row], 0.f);
    }
}

// ---------------- final features + FC ----------------
__global__ void final_kernel(const float* __restrict__ outs, const float* __restrict__ outg,
                             const float* __restrict__ x, const float* __restrict__ hout,
                             const int* __restrict__ span_idx,
                             const float* __restrict__ fcW, const float* __restrict__ fcb,
                             float* __restrict__ out)
{
    int b = blockIdx.x;
    int tid = threadIdx.x;                // 256
    __shared__ float feats[5*DD];
    int s = span_idx[b*8 + 0];
    int e = span_idx[b*8 + 1];
    for (int c = tid; c < DD; c += blockDim.x) {
        float t0 = 0.f, t1 = 0.f;
        for (int t = s; t < e; t++) {
            long long idx = ((long long)b*MAXL + t)*DD + c;
            t0 += outs[idx] + outg[idx];
            t1 += x[idx];
        }
        feats[c]        = hout[b*DD + c];
        feats[DD + c]   = t0;
        feats[2*DD + c] = t1;
        feats[3*DD + c] = t0 * t1;
        feats[4*DD + c] = fabsf(t0 - t1);
    }
    __syncthreads();
    float p0 = 0.f, p1 = 0.f, p2 = 0.f;
    for (int i = tid; i < 5*DD; i += blockDim.x) {
        float f = feats[i];
        p0 += f * fcW[i*3 + 0];
        p1 += f * fcW[i*3 + 1];
        p2 += f * fcW[i*3 + 2];
    }
    __shared__ float rbuf[3][8];
#pragma unroll
    for (int o = 16; o > 0; o >>= 1) {
        p0 += __shfl_xor_sync(0xffffffffu, p0, o);
        p1 += __shfl_xor_sync(0xffffffffu, p1, o);
        p2 += __shfl_xor_sync(0xffffffffu, p2, o);
    }
    if ((tid & 31) == 0) { rbuf[0][tid>>5] = p0; rbuf[1][tid>>5] = p1; rbuf[2][tid>>5] = p2; }
    __syncthreads();
    if (tid < 3) {
        float sres = 0.f;
#pragma unroll
        for (int w = 0; w < 8; w++) sres += rbuf[tid][w];
        out[b*3 + tid] = sres + fcb[tid];
    }
}

// ---------------- host-side helper ----------------
static void gemm(const float* A, int lda, long long sA,
                 const float* Bm, int ldb, long long sB,
                 const float* bias,
                 float* C, int ldc, long long sC,
                 int M, int N, int Kd, float alpha, int transB, int batch)
{
    dim3 g((M + BM - 1)/BM, (N + BN - 1)/BN, batch);
    sgemm_kernel<<<g, 256>>>(A, lda, sA, Bm, ldb, sB, bias, C, ldc, sC, M, N, Kd, alpha, transB);
}

extern "C" void kernel_launch(void* const* d_in, const int* in_sizes, int n_in,
                              void* d_out, int out_size)
{
    const float* bert    = (const float*)d_in[0];
    const float* adj1    = (const float*)d_in[1];
    const float* adj2    = (const float*)d_in[2];
    const float* Wih_f   = (const float*)d_in[3];
    const float* Whh_f   = (const float*)d_in[4];
    const float* b_f     = (const float*)d_in[5];
    const float* Wih_b   = (const float*)d_in[6];
    const float* Whh_b   = (const float*)d_in[7];
    const float* b_b     = (const float*)d_in[8];
    const float* gcW     = (const float*)d_in[9];
    const float* bWqkv   = (const float*)d_in[10];
    const float* bbqkv   = (const float*)d_in[11];
    const float* bWao    = (const float*)d_in[12];
    const float* bbao    = (const float*)d_in[13];
    const float* bln1g   = (const float*)d_in[14];
    const float* bln1b   = (const float*)d_in[15];
    const float* bWi     = (const float*)d_in[16];
    const float* bbi     = (const float*)d_in[17];
    const float* bWo     = (const float*)d_in[18];
    const float* bbo     = (const float*)d_in[19];
    const float* bln2g   = (const float*)d_in[20];
    const float* bln2b   = (const float*)d_in[21];
    const float* fcW     = (const float*)d_in[22];
    const float* fcb     = (const float*)d_in[23];
    const int*   tran_idx= (const int*)d_in[24];
    const int*   tran_len= (const int*)d_in[25];
    const int*   span_idx= (const int*)d_in[26];

    float* buf = nullptr;
    cudaGetSymbolAddress((void**)&buf, d_buf);

    float* tmps = buf + O_TMPS;
    float* xpf  = buf + O_XPF;
    float* xpb  = buf + O_XPB;
    float* xbuf = buf + O_X;
    float* hout = buf + O_HOUT;
    float* outs = buf + O_OUTS;
    float* outg = buf + O_OUTG;
    float* qkv  = buf + O_QKV;
    float* sc   = buf + O_SC;
    float* ctx  = buf + O_CTX;
    float* p1   = buf + O_P1;
    float* abuf = buf + O_A;
    float* hbuf = buf + O_H;
    float* adjb = buf + O_ADJ;
    float* den  = buf + O_DEN;
    float* ybuf = buf + O_Y;
    float* zbuf = buf + O_Z;

    const long long nTokD = (long long)NTOK * DD;        // 3,200,000
    const long long nAdj  = (long long)BB * MAXL * MAXL; // 8,000,000

    // 1. segment sums
    tmps_kernel<<<NTOK, 256>>>(bert, tran_idx, tmps);

    // 2. LSTM input projections (both directions, natural order)
    gemm(tmps, EMB, 0, Wih_f, 4*HH, 0, b_f, xpf, 4*HH, 0, NTOK, 4*HH, EMB, 1.f, 0, 1);
    gemm(tmps, EMB, 0, Wih_b, 4*HH, 0, b_b, xpb, 4*HH, 0, NTOK, 4*HH, EMB, 1.f, 0, 1);

    // 3. recurrence
    lstm_kernel<<<2*BB, 400>>>(xpf, xpb, Whh_f, Whh_b, tran_len, xbuf, hout);

    // 4. adjacency prep
    adj_kernel<<<(unsigned)((nAdj + 255)/256), 256>>>(adj1, adj2, adjb, nAdj);
    denom_kernel<<<NTOK, 256>>>(adjb, den);

    // 5. init both chains with x
    copy2_kernel<<<(unsigned)((nTokD + 255)/256), 256>>>(xbuf, outs, outg, nTokD);

    const float inv_sqrt_d = 0.07071067811865475f;   // 1/sqrt(200)

    for (int i = 0; i < KLAY; i++) {
        const float* Wqkv = bWqkv + (long long)i*DD*3*DD;
        const float* bqkv = bbqkv + (long long)i*3*DD;
        const float* Wao  = bWao  + (long long)i*DD*DD;
        const float* bao  = bbao  + (long long)i*DD;
        const float* g1   = bln1g + (long long)i*DD;
        const float* b1   = bln1b + (long long)i*DD;
        const float* Wi   = bWi   + (long long)i*DD*DD;
        const float* bi   = bbi   + (long long)i*DD;
        const float* Wo   = bWo   + (long long)i*DD*DD;
        const float* bo   = bbo   + (long long)i*DD;
        const float* g2   = bln2g + (long long)i*DD;
        const float* b2   = bln2b + (long long)i*DD;

        // attention branch
        gemm(outs, DD, 0, Wqkv, 3*DD, 0, bqkv, qkv, 3*DD, 0, NTOK, 3*DD, DD, 1.f, 0, 1);
        // scores[b] = q @ k^T * inv_sqrt_d  (NT batched)
        gemm(qkv,       3*DD, (long long)MAXL*3*DD,
             qkv + DD,  3*DD, (long long)MAXL*3*DD,
             nullptr, sc, MAXL, (long long)MAXL*MAXL,
             MAXL, MAXL, DD, inv_sqrt_d, 1, BB);
        softmax_kernel<<<NTOK, 256>>>(sc, tran_len);
        // ctx[b] = att @ v
        gemm(sc,         MAXL, (long long)MAXL*MAXL,
             qkv + 2*DD, 3*DD, (long long)MAXL*3*DD,
             nullptr, ctx, DD, (long long)MAXL*DD,
             MAXL, DD, MAXL, 1.f, 0, BB);
        gemm(ctx, DD, 0, Wao, DD, 0, bao, p1, DD, 0, NTOK, DD, DD, 1.f, 0, 1);
        ln_residual_kernel<<<NTOK, 256>>>(p1, outs, g1, b1, abuf);
        gemm(abuf, DD, 0, Wi, DD, 0, bi, hbuf, DD, 0, NTOK, DD, DD, 1.f, 0, 1);
        gelu_kernel<<<(unsigned)((nTokD + 255)/256), 256>>>(hbuf, nTokD);
        gemm(hbuf, DD, 0, Wo, DD, 0, bo, p1, DD, 0, NTOK, DD, DD, 1.f, 0, 1);
        ln_residual_kernel<<<NTOK, 256>>>(p1, abuf, g2, b2, outs);

        // GCN branch
        gemm(outg, DD, 0, gcW, DD, 0, nullptr, ybuf, DD, 0, NTOK, DD, DD, 1.f, 0, 1);
        gemm(adjb, MAXL, (long long)MAXL*MAXL,
             ybuf, DD,   (long long)MAXL*DD,
             nullptr, zbuf, DD, (long long)MAXL*DD,
             MAXL, DD, MAXL, 1.f, 0, BB);
        gcn_kernel<<<(unsigned)((nTokD + 255)/256), 256>>>(zbuf, den, outg, nTokD);
    }

    // 6. final features + fc
    final_kernel<<<BB, 256>>>(outs, outg, xbuf, hout, span_idx, fcW, fcb, (float*)d_out);
}

// round 3
// speedup vs baseline: 1.1885x; 1.1885x over previous
#include <cuda_runtime.h>
#include <cuda_bf16.h>
#include <math.h>

// ---------------- problem constants ----------------
#define BB     32
#define SS     1024
#define MAXL   500
#define EMB    768
#define HH     100
#define DD     200           // 2*H
#define KLAY   3
#define NTOK   (BB*MAXL)     // 16000

// ---------------- scratch buffer (static device global; no allocation) ----------------
#define O_TMPS  0LL
#define O_XPF   (O_TMPS + (long long)NTOK*EMB)
#define O_XPB   (O_XPF  + (long long)NTOK*4*HH)
#define O_X     (O_XPB  + (long long)NTOK*4*HH)
#define O_HOUT  (O_X    + (long long)NTOK*DD)
#define O_OUTS  (O_HOUT + (long long)BB*DD)
#define O_OUTG  (O_OUTS + (long long)NTOK*DD)
#define O_QKV   (O_OUTG + (long long)NTOK*DD)
#define O_SC    (O_QKV  + (long long)NTOK*3*DD)
#define O_CTX   (O_SC   + (long long)BB*MAXL*MAXL)
#define O_P1    (O_CTX  + (long long)NTOK*DD)
#define O_A     (O_P1   + (long long)NTOK*DD)
#define O_H     (O_A    + (long long)NTOK*DD)
#define O_ADJ   (O_H    + (long long)NTOK*DD)
#define O_DEN   (O_ADJ  + (long long)BB*MAXL*MAXL)
#define O_Y     (O_DEN  + (long long)NTOK)
#define O_Z     (O_Y    + (long long)NTOK*DD)
#define O_TOTAL (O_Z    + (long long)NTOK*DD)

__device__ float d_buf[O_TOTAL];

// ---------------- packed f32x2 helpers ----------------
__device__ __forceinline__ unsigned long long pack2(float x, float y) {
    unsigned long long r;
    asm("mov.b64 %0, {%1, %2};" : "=l"(r) : "f"(x), "f"(y));
    return r;
}
__device__ __forceinline__ float2 unpack2(unsigned long long v) {
    float2 f;
    asm("mov.b64 {%0, %1}, %2;" : "=f"(f.x), "=f"(f.y) : "l"(v));
    return f;
}
__device__ __forceinline__ void ffma2(unsigned long long& d, unsigned long long a, unsigned long long b) {
    asm("fma.rn.f32x2 %0, %1, %2, %0;" : "+l"(d) : "l"(a), "l"(b));
}

// ---------------- kernel: tmps = segment-sum of bert_out[:,1:,:] ----------------
__global__ void tmps_kernel(const float* __restrict__ bert, const int* __restrict__ tran_idx,
                            float* __restrict__ tmps)
{
    long long bl = blockIdx.x;                 // 0..15999
    int b = (int)(bl / MAXL);
    int s = tran_idx[bl*2 + 0];
    int e = tran_idx[bl*2 + 1];
    for (int c = threadIdx.x; c < EMB; c += blockDim.x) {
        float acc = 0.f;
        for (int t = s; t < e; t++) {
            acc += bert[((long long)b*SS + (t+1))*EMB + c];
        }
        tmps[bl*EMB + c] = acc;
    }
}

// ---------------- packed-FFMA2 tiled fp32 GEMM ----------------
// C[bz](M,N) = alpha * A[bz](M,K) @ (transB? B[bz]^T : B[bz]) + bias, op: 0 none, 1 gelu
#define BM 128
#define BN 128
#define BK 16
__global__ __launch_bounds__(256, 2)
void sgemm2_kernel(const float* __restrict__ A, int lda, long long sA,
                   const float* __restrict__ Bm, int ldb, long long sB,
                   const float* __restrict__ bias,
                   float* __restrict__ C, int ldc, long long sC,
                   int M, int N, int Kd, float alpha, int transB, int op)
{
    int bz = blockIdx.z;
    A  += (long long)bz * sA;
    Bm += (long long)bz * sB;
    C  += (long long)bz * sC;

    __shared__ __align__(16) float As[BK][BM];
    __shared__ __align__(16) float Bd[BK][2*BN];   // duplicated pairs (v,v)

    int tid = threadIdx.x;
    int tx = tid & 15;          // 0..15 -> N lanes
    int ty = tid >> 4;          // 0..15 -> M lanes
    int row0 = blockIdx.x * BM;
    int col0 = blockIdx.y * BN;

    unsigned long long acc[4][8];
#pragma unroll
    for (int i = 0; i < 4; i++)
#pragma unroll
        for (int j = 0; j < 8; j++) acc[i][j] = 0ULL;

    for (int k0 = 0; k0 < Kd; k0 += BK) {
        // ---- load A tile (BM rows x BK k) into As[k][m] ----
        {
            int r  = tid >> 1;
            int kb = (tid & 1) * 8;
            int grow = row0 + r;
            float v[8];
            if (grow < M && (k0 + BK) <= Kd) {
                const float* p = A + (long long)grow*lda + k0 + kb;
#pragma unroll
                for (int i = 0; i < 4; i++) {
                    float2 t = *reinterpret_cast<const float2*>(p + 2*i);
                    v[2*i] = t.x; v[2*i+1] = t.y;
                }
            } else {
#pragma unroll
                for (int i = 0; i < 8; i++) {
                    int gk = k0 + kb + i;
                    v[i] = (grow < M && gk < Kd) ? A[(long long)grow*lda + gk] : 0.f;
                }
            }
#pragma unroll
            for (int i = 0; i < 8; i++) As[kb + i][r] = v[i];
        }
        // ---- load B tile into Bd[k][2n] duplicated ----
        if (!transB) {
            int kk = tid >> 4;
            int nb = (tid & 15) * 8;
            int gk = k0 + kk;
            float v[8];
            if (gk < Kd && (col0 + nb + 8) <= N) {
                const float* p = Bm + (long long)gk*ldb + col0 + nb;
#pragma unroll
                for (int i = 0; i < 4; i++) {
                    float2 t = *reinterpret_cast<const float2*>(p + 2*i);
                    v[2*i] = t.x; v[2*i+1] = t.y;
                }
            } else {
#pragma unroll
                for (int i = 0; i < 8; i++) {
                    int gn = col0 + nb + i;
                    v[i] = (gk < Kd && gn < N) ? Bm[(long long)gk*ldb + gn] : 0.f;
                }
            }
#pragma unroll
            for (int p = 0; p < 4; p++) {
                *reinterpret_cast<float4*>(&Bd[kk][2*nb + 4*p]) =
                    make_float4(v[2*p], v[2*p], v[2*p+1], v[2*p+1]);
            }
        } else {
            int n  = tid >> 1;
            int kb = (tid & 1) * 8;
            int gn = col0 + n;
            float v[8];
            if (gn < N && (k0 + BK) <= Kd) {
                const float* p = Bm + (long long)gn*ldb + k0 + kb;
#pragma unroll
                for (int i = 0; i < 4; i++) {
                    float2 t = *reinterpret_cast<const float2*>(p + 2*i);
                    v[2*i] = t.x; v[2*i+1] = t.y;
                }
            } else {
#pragma unroll
                for (int i = 0; i < 8; i++) {
                    int gk = k0 + kb + i;
                    v[i] = (gn < N && gk < Kd) ? Bm[(long long)gn*ldb + gk] : 0.f;
                }
            }
#pragma unroll
            for (int i = 0; i < 8; i++) {
                *reinterpret_cast<float2*>(&Bd[kb + i][2*n]) = make_float2(v[i], v[i]);
            }
        }
        __syncthreads();

        // ---- compute: 8M x 8N per thread, M-pairs packed ----
#pragma unroll
        for (int kk = 0; kk < BK; kk++) {
            unsigned long long a2[4], b2[8];
#pragma unroll
            for (int i = 0; i < 4; i++)
                a2[i] = *reinterpret_cast<const unsigned long long*>(&As[kk][2*ty + 32*i]);
#pragma unroll
            for (int j = 0; j < 8; j++)
                b2[j] = *reinterpret_cast<const unsigned long long*>(&Bd[kk][2*(tx + 16*j)]);
#pragma unroll
            for (int i = 0; i < 4; i++)
#pragma unroll
                for (int j = 0; j < 8; j++)
                    ffma2(acc[i][j], a2[i], b2[j]);
        }
        __syncthreads();
    }

    // ---- epilogue ----
#pragma unroll
    for (int i = 0; i < 4; i++) {
        int m0 = row0 + 2*ty + 32*i;
#pragma unroll
        for (int j = 0; j < 8; j++) {
            int n = col0 + tx + 16*j;
            if (n >= N) continue;
            float2 r = unpack2(acc[i][j]);
            float bv = bias ? bias[n] : 0.f;
            float vlo = r.x * alpha + bv;
            float vhi = r.y * alpha + bv;
            if (op == 1) {
                vlo = 0.5f * vlo * (1.f + erff(vlo * 0.70710678118654752f));
                vhi = 0.5f * vhi * (1.f + erff(vhi * 0.70710678118654752f));
            }
            if (m0 < M)     C[(long long)m0*ldc + n]     = vlo;
            if (m0 + 1 < M) C[(long long)(m0+1)*ldc + n] = vhi;
        }
    }
}

// ---------------- LSTM recurrence: one block per (batch, direction), packed matvec ----------------
__global__ __launch_bounds__(400, 1)
void lstm_kernel(const float* __restrict__ xpf, const float* __restrict__ xpb,
                 const float* __restrict__ Whh_f, const float* __restrict__ Whh_b,
                 const int* __restrict__ tran_len,
                 float* __restrict__ x, float* __restrict__ hout)
{
    int b   = blockIdx.x >> 1;
    int dir = blockIdx.x & 1;
    const float* xp  = dir ? xpb : xpf;
    const float* Whh = dir ? Whh_b : Whh_f;
    int tl = tran_len[b];
    int j = threadIdx.x;  // 0..399

    unsigned long long w2[HH/2];
#pragma unroll
    for (int t = 0; t < HH/2; t++)
        w2[t] = pack2(Whh[(2*t)*4*HH + j], Whh[(2*t+1)*4*HH + j]);

    __shared__ __align__(16) float h[HH + 4];
    __shared__ __align__(16) float c[HH + 4];
    __shared__ float gates[4*HH];
    if (j < HH + 4) { h[j] = 0.f; c[j] = 0.f; }
    __syncthreads();

    const float* xpb_base = xp + (long long)b * MAXL * 4*HH;

    int pos0 = dir ? (MAXL - 1) : 0;
    float xcur = xpb_base[(long long)pos0*4*HH + j];

    for (int t = 0; t < MAXL; t++) {
        int pos = dir ? (MAXL - 1 - t) : t;
        float xnext = 0.f;
        if (t + 1 < MAXL) {
            int posn = dir ? (MAXL - 2 - t) : (t + 1);
            xnext = xpb_base[(long long)posn*4*HH + j];
        }
        float m = (pos < tl) ? 1.f : 0.f;

        unsigned long long g2a = 0ULL, g2b = 0ULL;
#pragma unroll
        for (int q = 0; q < HH/4; q++) {
            ulonglong2 hq = *reinterpret_cast<const ulonglong2*>(&h[4*q]);
            ffma2(g2a, w2[2*q],   hq.x);
            ffma2(g2b, w2[2*q+1], hq.y);
        }
        float2 ra = unpack2(g2a);
        float2 rb = unpack2(g2b);
        gates[j] = xcur + ((ra.x + ra.y) + (rb.x + rb.y));
        __syncthreads();

        if (j < HH) {
            float ig = gates[j], fg = gates[j+HH], cg = gates[j+2*HH], og = gates[j+3*HH];
            float si = 1.f / (1.f + __expf(-ig));
            float sf = 1.f / (1.f + __expf(-fg));
            float so = 1.f / (1.f + __expf(-og));
            float cn = sf * c[j] + si * tanhf(cg);
            float hn = so * tanhf(cn);
            float hj = m * hn + (1.f - m) * h[j];
            float cj = m * cn + (1.f - m) * c[j];
            h[j] = hj; c[j] = cj;
            x[((long long)b*MAXL + pos)*DD + dir*HH + j] = hj * m;
        }
        __syncthreads();
        xcur = xnext;
    }
    if (j < HH) hout[b*DD + dir*HH + j] = h[j];
}

// ---------------- fused adjacency clamp + row denominator ----------------
__global__ void adjden_kernel(const float* __restrict__ a1, const float* __restrict__ a2,
                              float* __restrict__ adj, float* __restrict__ den)
{
    long long row = blockIdx.x;               // 0..15999
    const float* p1 = a1 + row * MAXL;
    const float* p2 = a2 + row * MAXL;
    float* po = adj + row * MAXL;
    int cthr = threadIdx.x;                   // 256
    float s = 0.f;
    if (cthr < MAXL) {
        float v = fminf(p1[cthr] + p2[cthr], 1.f);
        po[cthr] = v; s += v;
    }
    if (cthr + 256 < MAXL) {
        float v = fminf(p1[cthr+256] + p2[cthr+256], 1.f);
        po[cthr+256] = v; s += v;
    }
    __shared__ float sred[8];
#pragma unroll
    for (int o = 16; o > 0; o >>= 1) s += __shfl_xor_sync(0xffffffffu, s, o);
    if ((cthr & 31) == 0) sred[cthr >> 5] = s;
    __syncthreads();
    if (cthr == 0) {
        float t = 0.f;
#pragma unroll
        for (int w = 0; w < 8; w++) t += sred[w];
        den[row] = t + 1e-7f;
    }
}

__global__ void copy2_kernel(const float* __restrict__ src, float* __restrict__ d1,
                             float* __restrict__ d2, long long n)
{
    long long i = (long long)blockIdx.x * blockDim.x + threadIdx.x;
    if (i < n) { float v = src[i]; d1[i] = v; d2[i] = v; }
}

__global__ void softmax_kernel(float* __restrict__ scores, const int* __restrict__ tran_len)
{
    long long row = blockIdx.x;           // 0..15999
    int b = (int)(row / MAXL);
    int tl = tran_len[b];
    float* s = scores + row * MAXL;
    int c  = threadIdx.x;                 // 256
    int c1 = c + 256;
    float v0 = -1e30f, v1 = -1e30f;
    if (c  < MAXL) v0 = s[c]  + (c  < tl ? 0.f : -10000.f);
    if (c1 < MAXL) v1 = s[c1] + (c1 < tl ? 0.f : -10000.f);
    float m = fmaxf(v0, v1);
    __shared__ float sred[8];
#pragma unroll
    for (int o = 16; o > 0; o >>= 1) m = fmaxf(m, __shfl_xor_sync(0xffffffffu, m, o));
    if ((c & 31) == 0) sred[c >> 5] = m;
    __syncthreads();
    float mm = sred[0];
#pragma unroll
    for (int w = 1; w < 8; w++) mm = fmaxf(mm, sred[w]);
    float e0 = (c  < MAXL) ? __expf(v0 - mm) : 0.f;
    float e1 = (c1 < MAXL) ? __expf(v1 - mm) : 0.f;
    float su = e0 + e1;
#pragma unroll
    for (int o = 16; o > 0; o >>= 1) su += __shfl_xor_sync(0xffffffffu, su, o);
    __syncthreads();
    if ((c & 31) == 0) sred[c >> 5] = su;
    __syncthreads();
    float tot = 0.f;
#pragma unroll
    for (int w = 0; w < 8; w++) tot += sred[w];
    float inv = 1.f / tot;
    if (c  < MAXL) s[c]  = e0 * inv;
    if (c1 < MAXL) s[c1] = e1 * inv;
}

__global__ void ln_residual_kernel(const float* __restrict__ p, const float* __restrict__ res,
                                   const float* __restrict__ g, const float* __restrict__ bb,
                                   float* __restrict__ out)
{
    long long r = blockIdx.x;             // 16000
    int c = threadIdx.x;                  // 256
    float v = 0.f;
    if (c < DD) v = p[r*DD + c] + res[r*DD + c];
    __shared__ float sred[8];
    float s = v;
#pragma unroll
    for (int o = 16; o > 0; o >>= 1) s += __shfl_xor_sync(0xffffffffu, s, o);
    if ((c & 31) == 0) sred[c >> 5] = s;
    __syncthreads();
    float tot = 0.f;
#pragma unroll
    for (int w = 0; w < 8; w++) tot += sred[w];
    float mean = tot * (1.f / DD);
    float dv = (c < DD) ? (v - mean) : 0.f;
    float s2 = dv * dv;
#pragma unroll
    for (int o = 16; o > 0; o >>= 1) s2 += __shfl_xor_sync(0xffffffffu, s2, o);
    __syncthreads();
    if ((c & 31) == 0) sred[c >> 5] = s2;
    __syncthreads();
    float v2 = 0.f;
#pragma unroll
    for (int w = 0; w < 8; w++) v2 += sred[w];
    float var = v2 * (1.f / DD);
    if (c < DD) out[r*DD + c] = dv * rsqrtf(var + 1e-20f) * g[c] + bb[c];
}

__global__ void gcn_kernel(const float* __restrict__ z, const float* __restrict__ den,
                           float* __restrict__ outg, long long n)
{
    long long i = (long long)blockIdx.x * blockDim.x + threadIdx.x;
    if (i < n) {
        long long row = i / DD;
        outg[i] += fmaxf(z[i] / den[row], 0.f);
    }
}

// ---------------- final features + FC ----------------
__global__ void final_kernel(const float* __restrict__ outs, const float* __restrict__ outg,
                             const float* __restrict__ x, const float* __restrict__ hout,
                             const int* __restrict__ span_idx,
                             const float* __restrict__ fcW, const float* __restrict__ fcb,
                             float* __restrict__ out)
{
    int b = blockIdx.x;
    int tid = threadIdx.x;                // 256
    __shared__ float feats[5*DD];
    int s = span_idx[b*8 + 0];
    int e = span_idx[b*8 + 1];
    for (int c = tid; c < DD; c += blockDim.x) {
        float t0 = 0.f, t1 = 0.f;
        for (int t = s; t < e; t++) {
            long long idx = ((long long)b*MAXL + t)*DD + c;
            t0 += outs[idx] + outg[idx];
            t1 += x[idx];
        }
        feats[c]        = hout[b*DD + c];
        feats[DD + c]   = t0;
        feats[2*DD + c] = t1;
        feats[3*DD + c] = t0 * t1;
        feats[4*DD + c] = fabsf(t0 - t1);
    }
    __syncthreads();
    float p0 = 0.f, p1 = 0.f, p2 = 0.f;
    for (int i = tid; i < 5*DD; i += blockDim.x) {
        float f = feats[i];
        p0 += f * fcW[i*3 + 0];
        p1 += f * fcW[i*3 + 1];
        p2 += f * fcW[i*3 + 2];
    }
    __shared__ float rbuf[3][8];
#pragma unroll
    for (int o = 16; o > 0; o >>= 1) {
        p0 += __shfl_xor_sync(0xffffffffu, p0, o);
        p1 += __shfl_xor_sync(0xffffffffu, p1, o);
        p2 += __shfl_xor_sync(0xffffffffu, p2, o);
    }
    if ((tid & 31) == 0) { rbuf[0][tid>>5] = p0; rbuf[1][tid>>5] = p1; rbuf[2][tid>>5] = p2; }
    __syncthreads();
    if (tid < 3) {
        float sres = 0.f;
#pragma unroll
        for (int w = 0; w < 8; w++) sres += rbuf[tid][w];
        out[b*3 + tid] = sres + fcb[tid];
    }
}

// ---------------- host-side helper ----------------
static void gemm(const float* A, int lda, long long sA,
                 const float* Bm, int ldb, long long sB,
                 const float* bias,
                 float* C, int ldc, long long sC,
                 int M, int N, int Kd, float alpha, int transB, int batch, int op = 0)
{
    dim3 g((M + BM - 1)/BM, (N + BN - 1)/BN, batch);
    sgemm2_kernel<<<g, 256>>>(A, lda, sA, Bm, ldb, sB, bias, C, ldc, sC, M, N, Kd, alpha, transB, op);
}

extern "C" void kernel_launch(void* const* d_in, const int* in_sizes, int n_in,
                              void* d_out, int out_size)
{
    const float* bert    = (const float*)d_in[0];
    const float* adj1    = (const float*)d_in[1];
    const float* adj2    = (const float*)d_in[2];
    const float* Wih_f   = (const float*)d_in[3];
    const float* Whh_f   = (const float*)d_in[4];
    const float* b_f     = (const float*)d_in[5];
    const float* Wih_b   = (const float*)d_in[6];
    const float* Whh_b   = (const float*)d_in[7];
    const float* b_b     = (const float*)d_in[8];
    const float* gcW     = (const float*)d_in[9];
    const float* bWqkv   = (const float*)d_in[10];
    const float* bbqkv   = (const float*)d_in[11];
    const float* bWao    = (const float*)d_in[12];
    const float* bbao    = (const float*)d_in[13];
    const float* bln1g   = (const float*)d_in[14];
    const float* bln1b   = (const float*)d_in[15];
    const float* bWi     = (const float*)d_in[16];
    const float* bbi     = (const float*)d_in[17];
    const float* bWo     = (const float*)d_in[18];
    const float* bbo     = (const float*)d_in[19];
    const float* bln2g   = (const float*)d_in[20];
    const float* bln2b   = (const float*)d_in[21];
    const float* fcW     = (const float*)d_in[22];
    const float* fcb     = (const float*)d_in[23];
    const int*   tran_idx= (const int*)d_in[24];
    const int*   tran_len= (const int*)d_in[25];
    const int*   span_idx= (const int*)d_in[26];

    float* buf = nullptr;
    cudaGetSymbolAddress((void**)&buf, d_buf);

    float* tmps = buf + O_TMPS;
    float* xpf  = buf + O_XPF;
    float* xpb  = buf + O_XPB;
    float* xbuf = buf + O_X;
    float* hout = buf + O_HOUT;
    float* outs = buf + O_OUTS;
    float* outg = buf + O_OUTG;
    float* qkv  = buf + O_QKV;
    float* sc   = buf + O_SC;
    float* ctx  = buf + O_CTX;
    float* p1   = buf + O_P1;
    float* abuf = buf + O_A;
    float* hbuf = buf + O_H;
    float* adjb = buf + O_ADJ;
    float* den  = buf + O_DEN;
    float* ybuf = buf + O_Y;
    float* zbuf = buf + O_Z;

    const long long nTokD = (long long)NTOK * DD;        // 3,200,000

    // 1. segment sums
    tmps_kernel<<<NTOK, 256>>>(bert, tran_idx, tmps);

    // 2. LSTM input projections
    gemm(tmps, EMB, 0, Wih_f, 4*HH, 0, b_f, xpf, 4*HH, 0, NTOK, 4*HH, EMB, 1.f, 0, 1);
    gemm(tmps, EMB, 0, Wih_b, 4*HH, 0, b_b, xpb, 4*HH, 0, NTOK, 4*HH, EMB, 1.f, 0, 1);

    // 3. recurrence
    lstm_kernel<<<2*BB, 400>>>(xpf, xpb, Whh_f, Whh_b, tran_len, xbuf, hout);

    // 4. adjacency prep (fused clamp + denom)
    adjden_kernel<<<NTOK, 256>>>(adj1, adj2, adjb, den);

    // 5. init both chains with x
    copy2_kernel<<<(unsigned)((nTokD + 255)/256), 256>>>(xbuf, outs, outg, nTokD);

    const float inv_sqrt_d = 0.07071067811865475f;   // 1/sqrt(200)

    for (int i = 0; i < KLAY; i++) {
        const float* Wqkv = bWqkv + (long long)i*DD*3*DD;
        const float* bqkv = bbqkv + (long long)i*3*DD;
        const float* Wao  = bWao  + (long long)i*DD*DD;
        const float* bao  = bbao  + (long long)i*DD;
        const float* g1   = bln1g + (long long)i*DD;
        const float* b1   = bln1b + (long long)i*DD;
        const float* Wi   = bWi   + (long long)i*DD*DD;
        const float* bi   = bbi   + (long long)i*DD;
        const float* Wo   = bWo   + (long long)i*DD*DD;
        const float* bo   = bbo   + (long long)i*DD;
        const float* g2   = bln2g + (long long)i*DD;
        const float* b2   = bln2b + (long long)i*DD;

        // attention branch
        gemm(outs, DD, 0, Wqkv, 3*DD, 0, bqkv, qkv, 3*DD, 0, NTOK, 3*DD, DD, 1.f, 0, 1);
        gemm(qkv,       3*DD, (long long)MAXL*3*DD,
             qkv + DD,  3*DD, (long long)MAXL*3*DD,
             nullptr, sc, MAXL, (long long)MAXL*MAXL,
             MAXL, MAXL, DD, inv_sqrt_d, 1, BB);
        softmax_kernel<<<NTOK, 256>>>(sc, tran_len);
        gemm(sc,         MAXL, (long long)MAXL*MAXL,
             qkv + 2*DD, 3*DD, (long long)MAXL*3*DD,
             nullptr, ctx, DD, (long long)MAXL*DD,
             MAXL, DD, MAXL, 1.f, 0, BB);
        gemm(ctx, DD, 0, Wao, DD, 0, bao, p1, DD, 0, NTOK, DD, DD, 1.f, 0, 1);
        ln_residual_kernel<<<NTOK, 256>>>(p1, outs, g1, b1, abuf);
        gemm(abuf, DD, 0, Wi, DD, 0, bi, hbuf, DD, 0, NTOK, DD, DD, 1.f, 0, 1, /*op=gelu*/1);
        gemm(hbuf, DD, 0, Wo, DD, 0, bo, p1, DD, 0, NTOK, DD, DD, 1.f, 0, 1);
        ln_residual_kernel<<<NTOK, 256>>>(p1, abuf, g2, b2, outs);

        // GCN branch
        gemm(outg, DD, 0, gcW, DD, 0, nullptr, ybuf, DD, 0, NTOK, DD, DD, 1.f, 0, 1);
        gemm(adjb, MAXL, (long long)MAXL*MAXL,
             ybuf, DD,   (long long)MAXL*DD,
             nullptr, zbuf, DD, (long long)MAXL*DD,
             MAXL, DD, MAXL, 1.f, 0, BB);
        gcn_kernel<<<(unsigned)((nTokD + 255)/256), 256>>>(zbuf, den, outg, nTokD);
    }

    // 6. final features + fc
    final_kernel<<<BB, 256>>>(outs, outg, xbuf, hout, span_idx, fcW, fcb, (float*)d_out);
}

// round 4
// speedup vs baseline: 1.6775x; 1.4115x over previous
#include <cuda_runtime.h>
#include <cuda_bf16.h>
#include <math.h>
#include <stdint.h>

// ---------------- problem constants ----------------
#define BB     32
#define SS     1024
#define MAXL   500
#define EMB    768
#define HH     100
#define DD     200           // 2*H
#define KLAY   3
#define NTOK   (BB*MAXL)     // 16000

// ---------------- scratch buffer (static device global; no allocation) ----------------
#define O_TMPS  0LL
#define O_XPF   (O_TMPS + (long long)NTOK*EMB)
#define O_XPB   (O_XPF  + (long long)NTOK*4*HH)
#define O_X     (O_XPB  + (long long)NTOK*4*HH)
#define O_HOUT  (O_X    + (long long)NTOK*DD)
#define O_OUTS  (O_HOUT + (long long)BB*DD)
#define O_OUTG  (O_OUTS + (long long)NTOK*DD)
#define O_QKV   (O_OUTG + (long long)NTOK*DD)
#define O_SC    (O_QKV  + (long long)NTOK*3*DD)
#define O_CTX   (O_SC   + (long long)BB*MAXL*MAXL)
#define O_P1    (O_CTX  + (long long)NTOK*DD)
#define O_A     (O_P1   + (long long)NTOK*DD)
#define O_H     (O_A    + (long long)NTOK*DD)
#define O_ADJ   (O_H    + (long long)NTOK*DD)
#define O_DEN   (O_ADJ  + (long long)BB*MAXL*MAXL)
#define O_Y     (O_DEN  + (long long)NTOK)
#define O_Z     (O_Y    + (long long)NTOK*DD)
#define O_TOTAL (O_Z    + (long long)NTOK*DD)

__device__ __align__(16) float d_buf[O_TOTAL];

// ---------------- helpers ----------------
__device__ __forceinline__ unsigned long long pack2(float x, float y) {
    unsigned long long r;
    asm("mov.b64 %0, {%1, %2};" : "=l"(r) : "f"(x), "f"(y));
    return r;
}
__device__ __forceinline__ float2 unpack2(unsigned long long v) {
    float2 f;
    asm("mov.b64 {%0, %1}, %2;" : "=f"(f.x), "=f"(f.y) : "l"(v));
    return f;
}
__device__ __forceinline__ void ffma2(unsigned long long& d, unsigned long long a, unsigned long long b) {
    asm("fma.rn.f32x2 %0, %1, %2, %0;" : "+l"(d) : "l"(a), "l"(b));
}
__device__ __forceinline__ float tf32_hi(float x) {
    uint32_t u;
    asm("cvt.rna.tf32.f32 %0, %1;" : "=r"(u) : "f"(x));
    return __uint_as_float(u);
}
__device__ __forceinline__ void mma_tf32(float* c, const uint32_t* a, const uint32_t* b) {
    asm volatile("mma.sync.aligned.m16n8k8.row.col.f32.tf32.tf32.f32 "
        "{%0,%1,%2,%3}, {%4,%5,%6,%7}, {%8,%9}, {%0,%1,%2,%3};\n"
        : "+f"(c[0]), "+f"(c[1]), "+f"(c[2]), "+f"(c[3])
        : "r"(a[0]), "r"(a[1]), "r"(a[2]), "r"(a[3]), "r"(b[0]), "r"(b[1]));
}

// ---------------- kernel: tmps = segment-sum of bert_out[:,1:,:] ----------------
__global__ void tmps_kernel(const float* __restrict__ bert, const int* __restrict__ tran_idx,
                            float* __restrict__ tmps)
{
    long long bl = blockIdx.x;                 // 0..15999
    int b = (int)(bl / MAXL);
    int s = tran_idx[bl*2 + 0];
    int e = tran_idx[bl*2 + 1];
    for (int c = threadIdx.x; c < EMB; c += blockDim.x) {
        float acc = 0.f;
        for (int t = s; t < e; t++) {
            acc += bert[((long long)b*SS + (t+1))*EMB + c];
        }
        tmps[bl*EMB + c] = acc;
    }
}

// ---------------- tf32 tensor-core GEMM (3x split for fp32 accuracy) ----------------
// C[bz](M,N) = alpha * A[bz](M,K) @ (transB? B^T : B) + bias
// op: 0 = store; 1 = gelu(store); 2 = C += relu(acc / aux[row])
#define GTM 128
#define GTN 128
#define GTK 16
__global__ __launch_bounds__(256)
void tgemm_kernel(const float* __restrict__ A, int lda, long long sA,
                  const float* __restrict__ Bm, int ldb, long long sB,
                  const float* __restrict__ bias,
                  const float* __restrict__ aux, int auxStride,
                  float* __restrict__ C, int ldc, long long sC,
                  int M, int N, int Kd, float alpha, int transB, int op)
{
    int bz = blockIdx.z;
    A  += (long long)bz * sA;
    Bm += (long long)bz * sB;
    C  += (long long)bz * sC;
    const float* auxp = aux ? (aux + (long long)bz * auxStride) : nullptr;

    __shared__ float Ah[GTK][GTM + 8];
    __shared__ float Al[GTK][GTM + 8];
    __shared__ float Bh[GTK][GTN + 8];
    __shared__ float Bl[GTK][GTN + 8];

    int tid  = threadIdx.x;
    int wid  = tid >> 5;
    int lane = tid & 31;
    int g  = lane >> 2;
    int tg = lane & 3;
    int wm = (wid & 3) * 32;       // warp m offset
    int wn = (wid >> 2) * 64;      // warp n offset

    int row0 = blockIdx.x * GTM;
    int col0 = blockIdx.y * GTN;

    float acc[2][8][4];
#pragma unroll
    for (int i = 0; i < 2; i++)
#pragma unroll
        for (int j = 0; j < 8; j++)
#pragma unroll
            for (int q = 0; q < 4; q++) acc[i][j][q] = 0.f;

    int kTiles = (Kd + GTK - 1) / GTK;
    for (int kt = 0; kt < kTiles; kt++) {
        int k0 = kt * GTK;
        // ---- stage A tile: thread r=tid>>1 loads 8 k's ----
        {
            int r  = tid >> 1;
            int kb = (tid & 1) * 8;
            int grow = row0 + r;
            float v[8];
            if (grow < M && (k0 + GTK) <= Kd) {
                const float* p = A + (long long)grow*lda + k0 + kb;
                float4 t0 = *reinterpret_cast<const float4*>(p);
                float4 t1 = *reinterpret_cast<const float4*>(p + 4);
                v[0]=t0.x; v[1]=t0.y; v[2]=t0.z; v[3]=t0.w;
                v[4]=t1.x; v[5]=t1.y; v[6]=t1.z; v[7]=t1.w;
            } else {
#pragma unroll
                for (int i = 0; i < 8; i++) {
                    int gk = k0 + kb + i;
                    v[i] = (grow < M && gk < Kd) ? A[(long long)grow*lda + gk] : 0.f;
                }
            }
#pragma unroll
            for (int i = 0; i < 8; i++) {
                float hi = tf32_hi(v[i]);
                Ah[kb + i][r] = hi;
                Al[kb + i][r] = v[i] - hi;
            }
        }
        // ---- stage B tile ----
        if (!transB) {
            int kk = tid >> 4;              // 0..15
            int nb = (tid & 15) * 8;
            int gk = k0 + kk;
            float v[8];
            if (gk < Kd && (col0 + nb + 8) <= N) {
                const float* p = Bm + (long long)gk*ldb + col0 + nb;
                float4 t0 = *reinterpret_cast<const float4*>(p);
                float4 t1 = *reinterpret_cast<const float4*>(p + 4);
                v[0]=t0.x; v[1]=t0.y; v[2]=t0.z; v[3]=t0.w;
                v[4]=t1.x; v[5]=t1.y; v[6]=t1.z; v[7]=t1.w;
            } else {
#pragma unroll
                for (int i = 0; i < 8; i++) {
                    int gn = col0 + nb + i;
                    v[i] = (gk < Kd && gn < N) ? Bm[(long long)gk*ldb + gn] : 0.f;
                }
            }
            float hv[8], lv[8];
#pragma unroll
            for (int i = 0; i < 8; i++) { hv[i] = tf32_hi(v[i]); lv[i] = v[i] - hv[i]; }
            *reinterpret_cast<float4*>(&Bh[kk][nb])     = make_float4(hv[0],hv[1],hv[2],hv[3]);
            *reinterpret_cast<float4*>(&Bh[kk][nb + 4]) = make_float4(hv[4],hv[5],hv[6],hv[7]);
            *reinterpret_cast<float4*>(&Bl[kk][nb])     = make_float4(lv[0],lv[1],lv[2],lv[3]);
            *reinterpret_cast<float4*>(&Bl[kk][nb + 4]) = make_float4(lv[4],lv[5],lv[6],lv[7]);
        } else {
            int n  = tid >> 1;
            int kb = (tid & 1) * 8;
            int gn = col0 + n;
            float v[8];
            if (gn < N && (k0 + GTK) <= Kd) {
                const float* p = Bm + (long long)gn*ldb + k0 + kb;
                float4 t0 = *reinterpret_cast<const float4*>(p);
                float4 t1 = *reinterpret_cast<const float4*>(p + 4);
                v[0]=t0.x; v[1]=t0.y; v[2]=t0.z; v[3]=t0.w;
                v[4]=t1.x; v[5]=t1.y; v[6]=t1.z; v[7]=t1.w;
            } else {
#pragma unroll
                for (int i = 0; i < 8; i++) {
                    int gk = k0 + kb + i;
                    v[i] = (gn < N && gk < Kd) ? Bm[(long long)gn*ldb + gk] : 0.f;
                }
            }
#pragma unroll
            for (int i = 0; i < 8; i++) {
                float hi = tf32_hi(v[i]);
                Bh[kb + i][n] = hi;
                Bl[kb + i][n] = v[i] - hi;
            }
        }
        __syncthreads();

        // ---- compute ----
#pragma unroll
        for (int ks = 0; ks < 2; ks++) {
            int kk = ks * 8;
            uint32_t ah[2][4], al[2][4];
#pragma unroll
            for (int i = 0; i < 2; i++) {
                int am = wm + i*16;
                ah[i][0] = __float_as_uint(Ah[kk+tg  ][am+g  ]);
                ah[i][1] = __float_as_uint(Ah[kk+tg  ][am+g+8]);
                ah[i][2] = __float_as_uint(Ah[kk+tg+4][am+g  ]);
                ah[i][3] = __float_as_uint(Ah[kk+tg+4][am+g+8]);
                al[i][0] = __float_as_uint(Al[kk+tg  ][am+g  ]);
                al[i][1] = __float_as_uint(Al[kk+tg  ][am+g+8]);
                al[i][2] = __float_as_uint(Al[kk+tg+4][am+g  ]);
                al[i][3] = __float_as_uint(Al[kk+tg+4][am+g+8]);
            }
            uint32_t bh[8][2], bl[8][2];
#pragma unroll
            for (int j = 0; j < 8; j++) {
                int bn = wn + j*8;
                bh[j][0] = __float_as_uint(Bh[kk+tg  ][bn+g]);
                bh[j][1] = __float_as_uint(Bh[kk+tg+4][bn+g]);
                bl[j][0] = __float_as_uint(Bl[kk+tg  ][bn+g]);
                bl[j][1] = __float_as_uint(Bl[kk+tg+4][bn+g]);
            }
#pragma unroll
            for (int i = 0; i < 2; i++)
#pragma unroll
                for (int j = 0; j < 8; j++) {
                    mma_tf32(acc[i][j], ah[i], bh[j]);
                    mma_tf32(acc[i][j], ah[i], bl[j]);
                    mma_tf32(acc[i][j], al[i], bh[j]);
                }
        }
        __syncthreads();
    }

    // ---- epilogue ----
#pragma unroll
    for (int i = 0; i < 2; i++) {
        int r0 = row0 + wm + i*16 + g;
        int r1 = r0 + 8;
#pragma unroll
        for (int j = 0; j < 8; j++) {
            int c0 = col0 + wn + j*8 + 2*tg;
            int c1 = c0 + 1;
            float v00 = acc[i][j][0], v01 = acc[i][j][1];
            float v10 = acc[i][j][2], v11 = acc[i][j][3];
            if (op == 2) {
                if (r0 < M) {
                    float inv = 1.f / auxp[r0];
                    if (c0 < N) C[(long long)r0*ldc + c0] += fmaxf(v00 * inv, 0.f);
                    if (c1 < N) C[(long long)r0*ldc + c1] += fmaxf(v01 * inv, 0.f);
                }
                if (r1 < M) {
                    float inv = 1.f / auxp[r1];
                    if (c0 < N) C[(long long)r1*ldc + c0] += fmaxf(v10 * inv, 0.f);
                    if (c1 < N) C[(long long)r1*ldc + c1] += fmaxf(v11 * inv, 0.f);
                }
            } else {
                float b0 = bias ? bias[c0 < N ? c0 : 0] : 0.f;
                float b1 = bias ? bias[c1 < N ? c1 : 0] : 0.f;
                v00 = v00 * alpha + b0; v01 = v01 * alpha + b1;
                v10 = v10 * alpha + b0; v11 = v11 * alpha + b1;
                if (op == 1) {
                    v00 = 0.5f * v00 * (1.f + erff(v00 * 0.70710678118654752f));
                    v01 = 0.5f * v01 * (1.f + erff(v01 * 0.70710678118654752f));
                    v10 = 0.5f * v10 * (1.f + erff(v10 * 0.70710678118654752f));
                    v11 = 0.5f * v11 * (1.f + erff(v11 * 0.70710678118654752f));
                }
                if (r0 < M) {
                    if (c0 < N) C[(long long)r0*ldc + c0] = v00;
                    if (c1 < N) C[(long long)r0*ldc + c1] = v01;
                }
                if (r1 < M) {
                    if (c0 < N) C[(long long)r1*ldc + c0] = v10;
                    if (c1 < N) C[(long long)r1*ldc + c1] = v11;
                }
            }
        }
    }
}

// ---------------- LSTM recurrence ----------------
// writes x, outs, outg (all = h*m) + hout final state
__global__ __launch_bounds__(400, 1)
void lstm_kernel(const float* __restrict__ xpf, const float* __restrict__ xpb,
                 const float* __restrict__ Whh_f, const float* __restrict__ Whh_b,
                 const int* __restrict__ tran_len,
                 float* __restrict__ x, float* __restrict__ outs, float* __restrict__ outg,
                 float* __restrict__ hout)
{
    int b   = blockIdx.x >> 1;
    int dir = blockIdx.x & 1;
    const float* xp  = dir ? xpb : xpf;
    const float* Whh = dir ? Whh_b : Whh_f;
    int tl = tran_len[b];
    int j = threadIdx.x;  // 0..399

    unsigned long long w2[HH/2];
#pragma unroll
    for (int t = 0; t < HH/2; t++)
        w2[t] = pack2(Whh[(2*t)*4*HH + j], Whh[(2*t+1)*4*HH + j]);

    __shared__ __align__(16) float h[HH + 4];
    __shared__ __align__(16) float c[HH + 4];
    __shared__ float act[4*HH];
    if (j < HH + 4) { h[j] = 0.f; c[j] = 0.f; }
    __syncthreads();

    const float* xpb_base = xp + (long long)b * MAXL * 4*HH;

    int pos0 = dir ? (MAXL - 1) : 0;
    float xcur = xpb_base[(long long)pos0*4*HH + j];
    bool is_cand = (j >= 2*HH) && (j < 3*HH);

    for (int t = 0; t < MAXL; t++) {
        int pos = dir ? (MAXL - 1 - t) : t;
        float xnext = 0.f;
        if (t + 1 < MAXL) {
            int posn = dir ? (MAXL - 2 - t) : (t + 1);
            xnext = xpb_base[(long long)posn*4*HH + j];
        }
        float m = (pos < tl) ? 1.f : 0.f;

        // matvec: 4 independent FFMA2 chains
        unsigned long long s0 = 0ULL, s1 = 0ULL, s2 = 0ULL, s3 = 0ULL;
#pragma unroll
        for (int q = 0; q < HH/8; q++) {          // 12 iters, k = 0..95
            ulonglong2 h0 = *reinterpret_cast<const ulonglong2*>(&h[8*q]);
            ulonglong2 h1 = *reinterpret_cast<const ulonglong2*>(&h[8*q + 4]);
            ffma2(s0, w2[4*q],     h0.x);
            ffma2(s1, w2[4*q + 1], h0.y);
            ffma2(s2, w2[4*q + 2], h1.x);
            ffma2(s3, w2[4*q + 3], h1.y);
        }
        {   // remainder k = 96..99
            ulonglong2 hr = *reinterpret_cast<const ulonglong2*>(&h[96]);
            ffma2(s0, w2[48], hr.x);
            ffma2(s1, w2[49], hr.y);
        }
        float2 r0 = unpack2(s0), r1 = unpack2(s1), r2 = unpack2(s2), r3 = unpack2(s3);
        float gv = xcur + (((r0.x + r0.y) + (r1.x + r1.y)) + ((r2.x + r2.y) + (r3.x + r3.y)));
        // per-gate nonlinearity in the wide phase
        act[j] = is_cand ? tanhf(gv) : (1.f / (1.f + __expf(-gv)));
        __syncthreads();

        if (j < HH) {
            float si = act[j], sf = act[j + HH], tc = act[j + 2*HH], so = act[j + 3*HH];
            float cn = sf * c[j] + si * tc;
            float hn = so * tanhf(cn);
            float hj = m * hn + (1.f - m) * h[j];
            float cj = m * cn + (1.f - m) * c[j];
            h[j] = hj; c[j] = cj;
            long long oidx = ((long long)b*MAXL + pos)*DD + dir*HH + j;
            float ov = hj * m;
            x[oidx] = ov; outs[oidx] = ov; outg[oidx] = ov;
        }
        __syncthreads();
        xcur = xnext;
    }
    if (j < HH) hout[b*DD + dir*HH + j] = h[j];
}

// ---------------- fused adjacency clamp + row denominator ----------------
__global__ void adjden_kernel(const float* __restrict__ a1, const float* __restrict__ a2,
                              float* __restrict__ adj, float* __restrict__ den)
{
    long long row = blockIdx.x;               // 0..15999
    const float* p1 = a1 + row * MAXL;
    const float* p2 = a2 + row * MAXL;
    float* po = adj + row * MAXL;
    int cthr = threadIdx.x;                   // 256
    float s = 0.f;
    if (cthr < MAXL) {
        float v = fminf(p1[cthr] + p2[cthr], 1.f);
        po[cthr] = v; s += v;
    }
    if (cthr + 256 < MAXL) {
        float v = fminf(p1[cthr+256] + p2[cthr+256], 1.f);
        po[cthr+256] = v; s += v;
    }
    __shared__ float sred[8];
#pragma unroll
    for (int o = 16; o > 0; o >>= 1) s += __shfl_xor_sync(0xffffffffu, s, o);
    if ((cthr & 31) == 0) sred[cthr >> 5] = s;
    __syncthreads();
    if (cthr == 0) {
        float t = 0.f;
#pragma unroll
        for (int w = 0; w < 8; w++) t += sred[w];
        den[row] = t + 1e-7f;
    }
}

__global__ void softmax_kernel(float* __restrict__ scores, const int* __restrict__ tran_len)
{
    long long row = blockIdx.x;           // 0..15999
    int b = (int)(row / MAXL);
    int tl = tran_len[b];
    float* s = scores + row * MAXL;
    int c  = threadIdx.x;                 // 256
    int c1 = c + 256;
    float v0 = -1e30f, v1 = -1e30f;
    if (c  < MAXL) v0 = s[c]  + (c  < tl ? 0.f : -10000.f);
    if (c1 < MAXL) v1 = s[c1] + (c1 < tl ? 0.f : -10000.f);
    float m = fmaxf(v0, v1);
    __shared__ float sred[8];
#pragma unroll
    for (int o = 16; o > 0; o >>= 1) m = fmaxf(m, __shfl_xor_sync(0xffffffffu, m, o));
    if ((c & 31) == 0) sred[c >> 5] = m;
    __syncthreads();
    float mm = sred[0];
#pragma unroll
    for (int w = 1; w < 8; w++) mm = fmaxf(mm, sred[w]);
    float e0 = (c  < MAXL) ? __expf(v0 - mm) : 0.f;
    float e1 = (c1 < MAXL) ? __expf(v1 - mm) : 0.f;
    float su = e0 + e1;
#pragma unroll
    for (int o = 16; o > 0; o >>= 1) su += __shfl_xor_sync(0xffffffffu, su, o);
    __syncthreads();
    if ((c & 31) == 0) sred[c >> 5] = su;
    __syncthreads();
    float tot = 0.f;
#pragma unroll
    for (int w = 0; w < 8; w++) tot += sred[w];
    float inv = 1.f / tot;
    if (c  < MAXL) s[c]  = e0 * inv;
    if (c1 < MAXL) s[c1] = e1 * inv;
}

__global__ void ln_residual_kernel(const float* __restrict__ p, const float* __restrict__ res,
                                   const float* __restrict__ g, const float* __restrict__ bb,
                                   float* __restrict__ out)
{
    long long r = blockIdx.x;             // 16000
    int c = threadIdx.x;                  // 256
    float v = 0.f;
    if (c < DD) v = p[r*DD + c] + res[r*DD + c];
    __shared__ float sred[8];
    float s = v;
#pragma unroll
    for (int o = 16; o > 0; o >>= 1) s += __shfl_xor_sync(0xffffffffu, s, o);
    if ((c & 31) == 0) sred[c >> 5] = s;
    __syncthreads();
    float tot = 0.f;
#pragma unroll
    for (int w = 0; w < 8; w++) tot += sred[w];
    float mean = tot * (1.f / DD);
    float dv = (c < DD) ? (v - mean) : 0.f;
    float s2 = dv * dv;
#pragma unroll
    for (int o = 16; o > 0; o >>= 1) s2 += __shfl_xor_sync(0xffffffffu, s2, o);
    __syncthreads();
    if ((c & 31) == 0) sred[c >> 5] = s2;
    __syncthreads();
    float v2 = 0.f;
#pragma unroll
    for (int w = 0; w < 8; w++) v2 += sred[w];
    float var = v2 * (1.f / DD);
    if (c < DD) out[r*DD + c] = dv * rsqrtf(var + 1e-20f) * g[c] + bb[c];
}

// ---------------- final features + FC ----------------
__global__ void final_kernel(const float* __restrict__ outs, const float* __restrict__ outg,
                             const float* __restrict__ x, const float* __restrict__ hout,
                             const int* __restrict__ span_idx,
                             const float* __restrict__ fcW, const float* __restrict__ fcb,
                             float* __restrict__ out)
{
    int b = blockIdx.x;
    int tid = threadIdx.x;                // 256
    __shared__ float feats[5*DD];
    int s = span_idx[b*8 + 0];
    int e = span_idx[b*8 + 1];
    for (int c = tid; c < DD; c += blockDim.x) {
        float t0 = 0.f, t1 = 0.f;
        for (int t = s; t < e; t++) {
            long long idx = ((long long)b*MAXL + t)*DD + c;
            t0 += outs[idx] + outg[idx];
            t1 += x[idx];
        }
        feats[c]        = hout[b*DD + c];
        feats[DD + c]   = t0;
        feats[2*DD + c] = t1;
        feats[3*DD + c] = t0 * t1;
        feats[4*DD + c] = fabsf(t0 - t1);
    }
    __syncthreads();
    float p0 = 0.f, p1 = 0.f, p2 = 0.f;
    for (int i = tid; i < 5*DD; i += blockDim.x) {
        float f = feats[i];
        p0 += f * fcW[i*3 + 0];
        p1 += f * fcW[i*3 + 1];
        p2 += f * fcW[i*3 + 2];
    }
    __shared__ float rbuf[3][8];
#pragma unroll
    for (int o = 16; o > 0; o >>= 1) {
        p0 += __shfl_xor_sync(0xffffffffu, p0, o);
        p1 += __shfl_xor_sync(0xffffffffu, p1, o);
        p2 += __shfl_xor_sync(0xffffffffu, p2, o);
    }
    if ((tid & 31) == 0) { rbuf[0][tid>>5] = p0; rbuf[1][tid>>5] = p1; rbuf[2][tid>>5] = p2; }
    __syncthreads();
    if (tid < 3) {
        float sres = 0.f;
#pragma unroll
        for (int w = 0; w < 8; w++) sres += rbuf[tid][w];
        out[b*3 + tid] = sres + fcb[tid];
    }
}

// ---------------- host-side helper ----------------
static void gemm(const float* A, int lda, long long sA,
                 const float* Bm, int ldb, long long sB,
                 const float* bias,
                 float* C, int ldc, long long sC,
                 int M, int N, int Kd, float alpha, int transB, int batch,
                 int op = 0, const float* aux = nullptr, int auxStride = 0)
{
    dim3 g((M + GTM - 1)/GTM, (N + GTN - 1)/GTN, batch);
    tgemm_kernel<<<g, 256>>>(A, lda, sA, Bm, ldb, sB, bias, aux, auxStride,
                             C, ldc, sC, M, N, Kd, alpha, transB, op);
}

extern "C" void kernel_launch(void* const* d_in, const int* in_sizes, int n_in,
                              void* d_out, int out_size)
{
    const float* bert    = (const float*)d_in[0];
    const float* adj1    = (const float*)d_in[1];
    const float* adj2    = (const float*)d_in[2];
    const float* Wih_f   = (const float*)d_in[3];
    const float* Whh_f   = (const float*)d_in[4];
    const float* b_f     = (const float*)d_in[5];
    const float* Wih_b   = (const float*)d_in[6];
    const float* Whh_b   = (const float*)d_in[7];
    const float* b_b     = (const float*)d_in[8];
    const float* gcW     = (const float*)d_in[9];
    const float* bWqkv   = (const float*)d_in[10];
    const float* bbqkv   = (const float*)d_in[11];
    const float* bWao    = (const float*)d_in[12];
    const float* bbao    = (const float*)d_in[13];
    const float* bln1g   = (const float*)d_in[14];
    const float* bln1b   = (const float*)d_in[15];
    const float* bWi     = (const float*)d_in[16];
    const float* bbi     = (const float*)d_in[17];
    const float* bWo     = (const float*)d_in[18];
    const float* bbo     = (const float*)d_in[19];
    const float* bln2g   = (const float*)d_in[20];
    const float* bln2b   = (const float*)d_in[21];
    const float* fcW     = (const float*)d_in[22];
    const float* fcb     = (const float*)d_in[23];
    const int*   tran_idx= (const int*)d_in[24];
    const int*   tran_len= (const int*)d_in[25];
    const int*   span_idx= (const int*)d_in[26];

    float* buf = nullptr;
    cudaGetSymbolAddress((void**)&buf, d_buf);

    float* tmps = buf + O_TMPS;
    float* xpf  = buf + O_XPF;
    float* xpb  = buf + O_XPB;
    float* xbuf = buf + O_X;
    float* hout = buf + O_HOUT;
    float* outs = buf + O_OUTS;
    float* outg = buf + O_OUTG;
    float* qkv  = buf + O_QKV;
    float* sc   = buf + O_SC;
    float* ctx  = buf + O_CTX;
    float* p1   = buf + O_P1;
    float* abuf = buf + O_A;
    float* hbuf = buf + O_H;
    float* adjb = buf + O_ADJ;
    float* den  = buf + O_DEN;
    float* ybuf = buf + O_Y;
    float* zbuf = buf + O_Z;
    (void)zbuf;

    // 1. segment sums
    tmps_kernel<<<NTOK, 256>>>(bert, tran_idx, tmps);

    // 2. LSTM input projections
    gemm(tmps, EMB, 0, Wih_f, 4*HH, 0, b_f, xpf, 4*HH, 0, NTOK, 4*HH, EMB, 1.f, 0, 1);
    gemm(tmps, EMB, 0, Wih_b, 4*HH, 0, b_b, xpb, 4*HH, 0, NTOK, 4*HH, EMB, 1.f, 0, 1);

    // 3. recurrence (writes x, outs, outg, hout)
    lstm_kernel<<<2*BB, 400>>>(xpf, xpb, Whh_f, Whh_b, tran_len, xbuf, outs, outg, hout);

    // 4. adjacency prep (fused clamp + denom)
    adjden_kernel<<<NTOK, 256>>>(adj1, adj2, adjb, den);

    const float inv_sqrt_d = 0.07071067811865475f;   // 1/sqrt(200)

    for (int i = 0; i < KLAY; i++) {
        const float* Wqkv = bWqkv + (long long)i*DD*3*DD;
        const float* bqkv = bbqkv + (long long)i*3*DD;
        const float* Wao  = bWao  + (long long)i*DD*DD;
        const float* bao  = bbao  + (long long)i*DD;
        const float* g1   = bln1g + (long long)i*DD;
        const float* b1   = bln1b + (long long)i*DD;
        const float* Wi   = bWi   + (long long)i*DD*DD;
        const float* bi   = bbi   + (long long)i*DD;
        const float* Wo   = bWo   + (long long)i*DD*DD;
        const float* bo   = bbo   + (long long)i*DD;
        const float* g2   = bln2g + (long long)i*DD;
        const float* b2   = bln2b + (long long)i*DD;

        // attention branch
        gemm(outs, DD, 0, Wqkv, 3*DD, 0, bqkv, qkv, 3*DD, 0, NTOK, 3*DD, DD, 1.f, 0, 1);
        gemm(qkv,       3*DD, (long long)MAXL*3*DD,
             qkv + DD,  3*DD, (long long)MAXL*3*DD,
             nullptr, sc, MAXL, (long long)MAXL*MAXL,
             MAXL, MAXL, DD, inv_sqrt_d, 1, BB);
        softmax_kernel<<<NTOK, 256>>>(sc, tran_len);
        gemm(sc,         MAXL, (long long)MAXL*MAXL,
             qkv + 2*DD, 3*DD, (long long)MAXL*3*DD,
             nullptr, ctx, DD, (long long)MAXL*DD,
             MAXL, DD, MAXL, 1.f, 0, BB);
        gemm(ctx, DD, 0, Wao, DD, 0, bao, p1, DD, 0, NTOK, DD, DD, 1.f, 0, 1);
        ln_residual_kernel<<<NTOK, 256>>>(p1, outs, g1, b1, abuf);
        gemm(abuf, DD, 0, Wi, DD, 0, bi, hbuf, DD, 0, NTOK, DD, DD, 1.f, 0, 1, /*gelu*/1);
        gemm(hbuf, DD, 0, Wo, DD, 0, bo, p1, DD, 0, NTOK, DD, DD, 1.f, 0, 1);
        ln_residual_kernel<<<NTOK, 256>>>(p1, abuf, g2, b2, outs);

        // GCN branch: y = outg @ gcW ; outg += relu((adj @ y)/den)  (fused epilogue)
        gemm(outg, DD, 0, gcW, DD, 0, nullptr, ybuf, DD, 0, NTOK, DD, DD, 1.f, 0, 1);
        gemm(adjb, MAXL, (long long)MAXL*MAXL,
             ybuf, DD,   (long long)MAXL*DD,
             nullptr, outg, DD, (long long)MAXL*DD,
             MAXL, DD, MAXL, 1.f, 0, BB,
             /*op=gcn*/2, den, MAXL);
    }

    // 6. final features + fc
    final_kernel<<<BB, 256>>>(outs, outg, xbuf, hout, span_idx, fcW, fcb, (float*)d_out);
}

// round 5
// speedup vs baseline: 1.9151x; 1.1416x over previous
#include <cuda_runtime.h>
#include <cuda_bf16.h>
#include <math.h>
#include <stdint.h>

// ---------------- problem constants ----------------
#define BB     32
#define SS     1024
#define MAXL   500
#define EMB    768
#define HH     100
#define DD     200           // 2*H
#define KLAY   3
#define NTOK   (BB*MAXL)     // 16000

// ---------------- scratch buffer ----------------
#define O_TMPS  0LL
#define O_XPF   (O_TMPS + (long long)NTOK*EMB)
#define O_XPB   (O_XPF  + (long long)NTOK*4*HH)
#define O_X     (O_XPB  + (long long)NTOK*4*HH)
#define O_HOUT  (O_X    + (long long)NTOK*DD)
#define O_OUTS  (O_HOUT + (long long)BB*DD)
#define O_OUTG  (O_OUTS + (long long)NTOK*DD)
#define O_QKV   (O_OUTG + (long long)NTOK*DD)
#define O_SC    (O_QKV  + (long long)NTOK*3*DD)
#define O_CTX   (O_SC   + (long long)BB*MAXL*MAXL)
#define O_P1    (O_CTX  + (long long)NTOK*DD)
#define O_A     (O_P1   + (long long)NTOK*DD)
#define O_H     (O_A    + (long long)NTOK*DD)
#define O_ADJ   (O_H    + (long long)NTOK*DD)
#define O_DEN   (O_ADJ  + (long long)BB*MAXL*MAXL)
#define O_Y     (O_DEN  + (long long)NTOK)
#define O_Z     (O_Y    + (long long)NTOK*DD)
#define O_TOTAL (O_Z    + (long long)NTOK*DD)

__device__ __align__(16) float d_buf[O_TOTAL];

// ---------------- helpers ----------------
__device__ __forceinline__ unsigned long long pack2(float x, float y) {
    unsigned long long r;
    asm("mov.b64 %0, {%1, %2};" : "=l"(r) : "f"(x), "f"(y));
    return r;
}
__device__ __forceinline__ float2 unpack2(unsigned long long v) {
    float2 f;
    asm("mov.b64 {%0, %1}, %2;" : "=f"(f.x), "=f"(f.y) : "l"(v));
    return f;
}
__device__ __forceinline__ void ffma2(unsigned long long& d, unsigned long long a, unsigned long long b) {
    asm("fma.rn.f32x2 %0, %1, %2, %0;" : "+l"(d) : "l"(a), "l"(b));
}
__device__ __forceinline__ float tf32_hi(float x) {
    uint32_t u;
    asm("cvt.rna.tf32.f32 %0, %1;" : "=r"(u) : "f"(x));
    return __uint_as_float(u);
}
__device__ __forceinline__ void mma_tf32(float* c, const uint32_t* a, const uint32_t* b) {
    asm volatile("mma.sync.aligned.m16n8k8.row.col.f32.tf32.tf32.f32 "
        "{%0,%1,%2,%3}, {%4,%5,%6,%7}, {%8,%9}, {%0,%1,%2,%3};\n"
        : "+f"(c[0]), "+f"(c[1]), "+f"(c[2]), "+f"(c[3])
        : "r"(a[0]), "r"(a[1]), "r"(a[2]), "r"(a[3]), "r"(b[0]), "r"(b[1]));
}
__device__ __forceinline__ uint32_t s2u(const void* p) {
    uint32_t a;
    asm("{ .reg .u64 t; cvta.to.shared.u64 t, %1; cvt.u32.u64 %0, t; }" : "=r"(a) : "l"(p));
    return a;
}
__device__ __forceinline__ void cp16(uint32_t dst, const float* src, bool v) {
    int sz = v ? 16 : 0;
    asm volatile("cp.async.cg.shared.global [%0], [%1], 16, %2;\n" :: "r"(dst), "l"(src), "r"(sz));
}
#define CP_COMMIT() asm volatile("cp.async.commit_group;\n")
// fast, accurate tanh: (e^{2x}-1)/(e^{2x}+1), abs err ~1e-7
__device__ __forceinline__ float tanh_acc(float x) {
    float ax = fminf(fabsf(x), 15.f);
    float t = __expf(2.f * ax);
    float r = __fdividef(t - 1.f, t + 1.f);
    return copysignf(r, x);
}

// ---------------- kernel: tmps = segment-sum of bert_out[:,1:,:] ----------------
__global__ void tmps_kernel(const float* __restrict__ bert, const int* __restrict__ tran_idx,
                            float* __restrict__ tmps)
{
    long long bl = blockIdx.x;                 // 0..15999
    int b = (int)(bl / MAXL);
    int s = tran_idx[bl*2 + 0];
    int e = tran_idx[bl*2 + 1];
    for (int c = threadIdx.x; c < EMB; c += blockDim.x) {
        float acc = 0.f;
        for (int t = s; t < e; t++) {
            acc += bert[((long long)b*SS + (t+1))*EMB + c];
        }
        tmps[bl*EMB + c] = acc;
    }
}

// ---------------- tf32 tensor-core GEMM, cp.async double-buffered ----------------
// C[bz](M,N) = alpha * A[bz](M,K) @ (transB? B^T : B) + bias
// op: 0 = store; 1 = gelu(store); 2 = C += relu(acc / aux[row])
#define GTM 128
#define GTN 128
#define GTK 16
#define APAD 20          // [m][k] / [n][k] row pitch (conflict-free)
#define BPADN 136        // [k][n] row pitch (conflict-free)
#define SBUF 2560        // floats per stage per array (128*20)
__global__ __launch_bounds__(256, 2)
void tgemm_kernel(const float* __restrict__ A, int lda, long long sA,
                  const float* __restrict__ Bm, int ldb, long long sB,
                  const float* __restrict__ bias,
                  const float* __restrict__ aux, int auxStride,
                  float* __restrict__ C, int ldc, long long sC,
                  int M, int N, int Kd, float alpha, int transB, int op)
{
    int bz = blockIdx.z;
    A  += (long long)bz * sA;
    Bm += (long long)bz * sB;
    C  += (long long)bz * sC;
    const float* auxp = aux ? (aux + (long long)bz * auxStride) : nullptr;

    __shared__ __align__(16) float As[2][SBUF];
    __shared__ __align__(16) float Bs[2][SBUF];

    int tid  = threadIdx.x;
    int wid  = tid >> 5;
    int lane = tid & 31;
    int g  = lane >> 2;
    int tg = lane & 3;
    int wm = (wid & 3) * 32;       // warp m offset
    int wn = (wid >> 2) * 64;      // warp n offset

    int row0 = blockIdx.x * GTM;
    int col0 = blockIdx.y * GTN;

    uint32_t sA0 = s2u(&As[0][0]);
    uint32_t sB0 = s2u(&Bs[0][0]);

    float acc[2][8][4];
#pragma unroll
    for (int i = 0; i < 2; i++)
#pragma unroll
        for (int j = 0; j < 8; j++)
#pragma unroll
            for (int q = 0; q < 4; q++) acc[i][j][q] = 0.f;

    int kTiles = (Kd + GTK - 1) / GTK;

    // ---- staging lambdas (2 chunks per thread per array) ----
    auto stageA = [&](int st, int kt) {
        int k0 = kt * GTK;
        uint32_t base = sA0 + st * SBUF * 4;
#pragma unroll
        for (int h = 0; h < 2; h++) {
            int c = tid + h * 256;           // 0..511
            int r  = c >> 2;
            int kc = c & 3;
            int grow = row0 + r;
            bool v = (grow < M) && (k0 + kc*4 < Kd);
            const float* src = v ? (A + (long long)grow*lda + k0 + kc*4) : A;
            cp16(base + (r*APAD + kc*4)*4, src, v);
        }
    };
    auto stageB = [&](int st, int kt) {
        int k0 = kt * GTK;
        uint32_t base = sB0 + st * SBUF * 4;
        if (transB) {
#pragma unroll
            for (int h = 0; h < 2; h++) {
                int c = tid + h * 256;
                int n  = c >> 2;
                int kc = c & 3;
                int gn = col0 + n;
                bool v = (gn < N) && (k0 + kc*4 < Kd);
                const float* src = v ? (Bm + (long long)gn*ldb + k0 + kc*4) : Bm;
                cp16(base + (n*APAD + kc*4)*4, src, v);
            }
        } else {
#pragma unroll
            for (int h = 0; h < 2; h++) {
                int c = tid + h * 256;
                int k  = c >> 5;
                int nc = c & 31;
                int gn = col0 + nc*4;
                bool v = (k0 + k < Kd) && (gn < N);
                const float* src = v ? (Bm + (long long)(k0+k)*ldb + gn) : Bm;
                cp16(base + (k*BPADN + nc*4)*4, src, v);
            }
        }
    };

    stageA(0, 0); stageB(0, 0); CP_COMMIT();

    for (int kt = 0; kt < kTiles; kt++) {
        int cur = kt & 1;
        if (kt + 1 < kTiles) {
            stageA(cur ^ 1, kt + 1);
            stageB(cur ^ 1, kt + 1);
            CP_COMMIT();
            asm volatile("cp.async.wait_group 1;\n");
        } else {
            asm volatile("cp.async.wait_group 0;\n");
        }
        __syncthreads();

        const float* as = As[cur];
        const float* bs = Bs[cur];
#pragma unroll
        for (int ks = 0; ks < 2; ks++) {
            int kk = ks * 8;
            uint32_t ah[2][4], al[2][4];
#pragma unroll
            for (int i = 0; i < 2; i++) {
                int am = wm + i*16;
                float r0 = as[(am+g  )*APAD + kk+tg  ];
                float r1 = as[(am+g+8)*APAD + kk+tg  ];
                float r2 = as[(am+g  )*APAD + kk+tg+4];
                float r3 = as[(am+g+8)*APAD + kk+tg+4];
                float h0 = tf32_hi(r0), h1 = tf32_hi(r1), h2 = tf32_hi(r2), h3 = tf32_hi(r3);
                ah[i][0] = __float_as_uint(h0); al[i][0] = __float_as_uint(r0 - h0);
                ah[i][1] = __float_as_uint(h1); al[i][1] = __float_as_uint(r1 - h1);
                ah[i][2] = __float_as_uint(h2); al[i][2] = __float_as_uint(r2 - h2);
                ah[i][3] = __float_as_uint(h3); al[i][3] = __float_as_uint(r3 - h3);
            }
#pragma unroll
            for (int j = 0; j < 8; j++) {
                int bn = wn + j*8;
                float r0, r1;
                if (transB) {
                    r0 = bs[(bn+g)*APAD + kk+tg  ];
                    r1 = bs[(bn+g)*APAD + kk+tg+4];
                } else {
                    r0 = bs[(kk+tg  )*BPADN + bn+g];
                    r1 = bs[(kk+tg+4)*BPADN + bn+g];
                }
                float h0 = tf32_hi(r0), h1 = tf32_hi(r1);
                uint32_t bh[2] = { __float_as_uint(h0), __float_as_uint(h1) };
                uint32_t bl[2] = { __float_as_uint(r0 - h0), __float_as_uint(r1 - h1) };
                mma_tf32(acc[0][j], ah[0], bh);
                mma_tf32(acc[0][j], ah[0], bl);
                mma_tf32(acc[0][j], al[0], bh);
                mma_tf32(acc[1][j], ah[1], bh);
                mma_tf32(acc[1][j], ah[1], bl);
                mma_tf32(acc[1][j], al[1], bh);
            }
        }
        __syncthreads();
    }

    // ---- epilogue ----
#pragma unroll
    for (int i = 0; i < 2; i++) {
        int r0 = row0 + wm + i*16 + g;
        int r1 = r0 + 8;
#pragma unroll
        for (int j = 0; j < 8; j++) {
            int c0 = col0 + wn + j*8 + 2*tg;
            int c1 = c0 + 1;
            float v00 = acc[i][j][0], v01 = acc[i][j][1];
            float v10 = acc[i][j][2], v11 = acc[i][j][3];
            if (op == 2) {
                if (r0 < M) {
                    float inv = 1.f / auxp[r0];
                    if (c0 < N) C[(long long)r0*ldc + c0] += fmaxf(v00 * inv, 0.f);
                    if (c1 < N) C[(long long)r0*ldc + c1] += fmaxf(v01 * inv, 0.f);
                }
                if (r1 < M) {
                    float inv = 1.f / auxp[r1];
                    if (c0 < N) C[(long long)r1*ldc + c0] += fmaxf(v10 * inv, 0.f);
                    if (c1 < N) C[(long long)r1*ldc + c1] += fmaxf(v11 * inv, 0.f);
                }
            } else {
                float b0 = bias ? bias[c0 < N ? c0 : 0] : 0.f;
                float b1 = bias ? bias[c1 < N ? c1 : 0] : 0.f;
                v00 = v00 * alpha + b0; v01 = v01 * alpha + b1;
                v10 = v10 * alpha + b0; v11 = v11 * alpha + b1;
                if (op == 1) {
                    v00 = 0.5f * v00 * (1.f + erff(v00 * 0.70710678118654752f));
                    v01 = 0.5f * v01 * (1.f + erff(v01 * 0.70710678118654752f));
                    v10 = 0.5f * v10 * (1.f + erff(v10 * 0.70710678118654752f));
                    v11 = 0.5f * v11 * (1.f + erff(v11 * 0.70710678118654752f));
                }
                if (r0 < M) {
                    if (c0 < N) C[(long long)r0*ldc + c0] = v00;
                    if (c1 < N) C[(long long)r0*ldc + c1] = v01;
                }
                if (r1 < M) {
                    if (c0 < N) C[(long long)r1*ldc + c0] = v10;
                    if (c1 < N) C[(long long)r1*ldc + c1] = v11;
                }
            }
        }
    }
}

// ---------------- LSTM recurrence ----------------
__global__ __launch_bounds__(400, 1)
void lstm_kernel(const float* __restrict__ xpf, const float* __restrict__ xpb,
                 const float* __restrict__ Whh_f, const float* __restrict__ Whh_b,
                 const int* __restrict__ tran_len,
                 float* __restrict__ x, float* __restrict__ outs, float* __restrict__ outg,
                 float* __restrict__ hout)
{
    int b   = blockIdx.x >> 1;
    int dir = blockIdx.x & 1;
    const float* xp  = dir ? xpb : xpf;
    const float* Whh = dir ? Whh_b : Whh_f;
    int tl = tran_len[b];
    int j = threadIdx.x;  // 0..399

    unsigned long long w2[HH/2];
#pragma unroll
    for (int t = 0; t < HH/2; t++)
        w2[t] = pack2(Whh[(2*t)*4*HH + j], Whh[(2*t+1)*4*HH + j]);

    __shared__ __align__(16) float h[HH + 4];
    __shared__ __align__(16) float c[HH + 4];
    __shared__ float act[4*HH];
    if (j < HH + 4) { h[j] = 0.f; c[j] = 0.f; }
    __syncthreads();

    const float* xpb_base = xp + (long long)b * MAXL * 4*HH;

    int pos0 = dir ? (MAXL - 1) : 0;
    float xcur = xpb_base[(long long)pos0*4*HH + j];
    bool is_cand = (j >= 2*HH) && (j < 3*HH);

    for (int t = 0; t < MAXL; t++) {
        int pos = dir ? (MAXL - 1 - t) : t;
        float xnext = 0.f;
        if (t + 1 < MAXL) {
            int posn = dir ? (MAXL - 2 - t) : (t + 1);
            xnext = xpb_base[(long long)posn*4*HH + j];
        }
        float m = (pos < tl) ? 1.f : 0.f;

        unsigned long long s0 = 0ULL, s1 = 0ULL, s2 = 0ULL, s3 = 0ULL;
#pragma unroll
        for (int q = 0; q < HH/8; q++) {          // 12 iters, k = 0..95
            ulonglong2 h0 = *reinterpret_cast<const ulonglong2*>(&h[8*q]);
            ulonglong2 h1 = *reinterpret_cast<const ulonglong2*>(&h[8*q + 4]);
            ffma2(s0, w2[4*q],     h0.x);
            ffma2(s1, w2[4*q + 1], h0.y);
            ffma2(s2, w2[4*q + 2], h1.x);
            ffma2(s3, w2[4*q + 3], h1.y);
        }
        {   // remainder k = 96..99
            ulonglong2 hr = *reinterpret_cast<const ulonglong2*>(&h[96]);
            ffma2(s0, w2[48], hr.x);
            ffma2(s1, w2[49], hr.y);
        }
        float2 r0 = unpack2(s0), r1 = unpack2(s1), r2 = unpack2(s2), r3 = unpack2(s3);
        float gv = xcur + (((r0.x + r0.y) + (r1.x + r1.y)) + ((r2.x + r2.y) + (r3.x + r3.y)));
        act[j] = is_cand ? tanh_acc(gv) : (1.f / (1.f + __expf(-gv)));
        __syncthreads();

        if (j < HH) {
            float si = act[j], sf = act[j + HH], tc = act[j + 2*HH], so = act[j + 3*HH];
            float cn = sf * c[j] + si * tc;
            float hn = so * tanh_acc(cn);
            float hj = m * hn + (1.f - m) * h[j];
            float cj = m * cn + (1.f - m) * c[j];
            h[j] = hj; c[j] = cj;
            long long oidx = ((long long)b*MAXL + pos)*DD + dir*HH + j;
            float ov = hj * m;
            x[oidx] = ov; outs[oidx] = ov; outg[oidx] = ov;
        }
        __syncthreads();
        xcur = xnext;
    }
    if (j < HH) hout[b*DD + dir*HH + j] = h[j];
}

// ---------------- fused adjacency clamp + row denominator ----------------
__global__ void adjden_kernel(const float* __restrict__ a1, const float* __restrict__ a2,
                              float* __restrict__ adj, float* __restrict__ den)
{
    long long row = blockIdx.x;               // 0..15999
    const float* p1 = a1 + row * MAXL;
    const float* p2 = a2 + row * MAXL;
    float* po = adj + row * MAXL;
    int cthr = threadIdx.x;                   // 256
    float s = 0.f;
    if (cthr < MAXL) {
        float v = fminf(p1[cthr] + p2[cthr], 1.f);
        po[cthr] = v; s += v;
    }
    if (cthr + 256 < MAXL) {
        float v = fminf(p1[cthr+256] + p2[cthr+256], 1.f);
        po[cthr+256] = v; s += v;
    }
    __shared__ float sred[8];
#pragma unroll
    for (int o = 16; o > 0; o >>= 1) s += __shfl_xor_sync(0xffffffffu, s, o);
    if ((cthr & 31) == 0) sred[cthr >> 5] = s;
    __syncthreads();
    if (cthr == 0) {
        float t = 0.f;
#pragma unroll
        for (int w = 0; w < 8; w++) t += sred[w];
        den[row] = t + 1e-7f;
    }
}

__global__ void softmax_kernel(float* __restrict__ scores, const int* __restrict__ tran_len)
{
    long long row = blockIdx.x;           // 0..15999
    int b = (int)(row / MAXL);
    int tl = tran_len[b];
    float* s = scores + row * MAXL;
    int c  = threadIdx.x;                 // 256
    int c1 = c + 256;
    float v0 = -1e30f, v1 = -1e30f;
    if (c  < MAXL) v0 = s[c]  + (c  < tl ? 0.f : -10000.f);
    if (c1 < MAXL) v1 = s[c1] + (c1 < tl ? 0.f : -10000.f);
    float m = fmaxf(v0, v1);
    __shared__ float sred[8];
#pragma unroll
    for (int o = 16; o > 0; o >>= 1) m = fmaxf(m, __shfl_xor_sync(0xffffffffu, m, o));
    if ((c & 31) == 0) sred[c >> 5] = m;
    __syncthreads();
    float mm = sred[0];
#pragma unroll
    for (int w = 1; w < 8; w++) mm = fmaxf(mm, sred[w]);
    float e0 = (c  < MAXL) ? __expf(v0 - mm) : 0.f;
    float e1 = (c1 < MAXL) ? __expf(v1 - mm) : 0.f;
    float su = e0 + e1;
#pragma unroll
    for (int o = 16; o > 0; o >>= 1) su += __shfl_xor_sync(0xffffffffu, su, o);
    __syncthreads();
    if ((c & 31) == 0) sred[c >> 5] = su;
    __syncthreads();
    float tot = 0.f;
#pragma unroll
    for (int w = 0; w < 8; w++) tot += sred[w];
    float inv = 1.f / tot;
    if (c  < MAXL) s[c]  = e0 * inv;
    if (c1 < MAXL) s[c1] = e1 * inv;
}

__global__ void ln_residual_kernel(const float* __restrict__ p, const float* __restrict__ res,
                                   const float* __restrict__ g, const float* __restrict__ bb,
                                   float* __restrict__ out)
{
    long long r = blockIdx.x;             // 16000
    int c = threadIdx.x;                  // 256
    float v = 0.f;
    if (c < DD) v = p[r*DD + c] + res[r*DD + c];
    __shared__ float sred[8];
    float s = v;
#pragma unroll
    for (int o = 16; o > 0; o >>= 1) s += __shfl_xor_sync(0xffffffffu, s, o);
    if ((c & 31) == 0) sred[c >> 5] = s;
    __syncthreads();
    float tot = 0.f;
#pragma unroll
    for (int w = 0; w < 8; w++) tot += sred[w];
    float mean = tot * (1.f / DD);
    float dv = (c < DD) ? (v - mean) : 0.f;
    float s2 = dv * dv;
#pragma unroll
    for (int o = 16; o > 0; o >>= 1) s2 += __shfl_xor_sync(0xffffffffu, s2, o);
    __syncthreads();
    if ((c & 31) == 0) sred[c >> 5] = s2;
    __syncthreads();
    float v2 = 0.f;
#pragma unroll
    for (int w = 0; w < 8; w++) v2 += sred[w];
    float var = v2 * (1.f / DD);
    if (c < DD) out[r*DD + c] = dv * rsqrtf(var + 1e-20f) * g[c] + bb[c];
}

// ---------------- final features + FC ----------------
__global__ void final_kernel(const float* __restrict__ outs, const float* __restrict__ outg,
                             const float* __restrict__ x, const float* __restrict__ hout,
                             const int* __restrict__ span_idx,
                             const float* __restrict__ fcW, const float* __restrict__ fcb,
                             float* __restrict__ out)
{
    int b = blockIdx.x;
    int tid = threadIdx.x;                // 256
    __shared__ float feats[5*DD];
    int s = span_idx[b*8 + 0];
    int e = span_idx[b*8 + 1];
    for (int c = tid; c < DD; c += blockDim.x) {
        float t0 = 0.f, t1 = 0.f;
        for (int t = s; t < e; t++) {
            long long idx = ((long long)b*MAXL + t)*DD + c;
            t0 += outs[idx] + outg[idx];
            t1 += x[idx];
        }
        feats[c]        = hout[b*DD + c];
        feats[DD + c]   = t0;
        feats[2*DD + c] = t1;
        feats[3*DD + c] = t0 * t1;
        feats[4*DD + c] = fabsf(t0 - t1);
    }
    __syncthreads();
    float p0 = 0.f, p1 = 0.f, p2 = 0.f;
    for (int i = tid; i < 5*DD; i += blockDim.x) {
        float f = feats[i];
        p0 += f * fcW[i*3 + 0];
        p1 += f * fcW[i*3 + 1];
        p2 += f * fcW[i*3 + 2];
    }
    __shared__ float rbuf[3][8];
#pragma unroll
    for (int o = 16; o > 0; o >>= 1) {
        p0 += __shfl_xor_sync(0xffffffffu, p0, o);
        p1 += __shfl_xor_sync(0xffffffffu, p1, o);
        p2 += __shfl_xor_sync(0xffffffffu, p2, o);
    }
    if ((tid & 31) == 0) { rbuf[0][tid>>5] = p0; rbuf[1][tid>>5] = p1; rbuf[2][tid>>5] = p2; }
    __syncthreads();
    if (tid < 3) {
        float sres = 0.f;
#pragma unroll
        for (int w = 0; w < 8; w++) sres += rbuf[tid][w];
        out[b*3 + tid] = sres + fcb[tid];
    }
}

// ---------------- host-side helper ----------------
static void gemm(const float* A, int lda, long long sA,
                 const float* Bm, int ldb, long long sB,
                 const float* bias,
                 float* C, int ldc, long long sC,
                 int M, int N, int Kd, float alpha, int transB, int batch,
                 int op = 0, const float* aux = nullptr, int auxStride = 0)
{
    dim3 g((M + GTM - 1)/GTM, (N + GTN - 1)/GTN, batch);
    tgemm_kernel<<<g, 256>>>(A, lda, sA, Bm, ldb, sB, bias, aux, auxStride,
                             C, ldc, sC, M, N, Kd, alpha, transB, op);
}

extern "C" void kernel_launch(void* const* d_in, const int* in_sizes, int n_in,
                              void* d_out, int out_size)
{
    const float* bert    = (const float*)d_in[0];
    const float* adj1    = (const float*)d_in[1];
    const float* adj2    = (const float*)d_in[2];
    const float* Wih_f   = (const float*)d_in[3];
    const float* Whh_f   = (const float*)d_in[4];
    const float* b_f     = (const float*)d_in[5];
    const float* Wih_b   = (const float*)d_in[6];
    const float* Whh_b   = (const float*)d_in[7];
    const float* b_b     = (const float*)d_in[8];
    const float* gcW     = (const float*)d_in[9];
    const float* bWqkv   = (const float*)d_in[10];
    const float* bbqkv   = (const float*)d_in[11];
    const float* bWao    = (const float*)d_in[12];
    const float* bbao    = (const float*)d_in[13];
    const float* bln1g   = (const float*)d_in[14];
    const float* bln1b   = (const float*)d_in[15];
    const float* bWi     = (const float*)d_in[16];
    const float* bbi     = (const float*)d_in[17];
    const float* bWo     = (const float*)d_in[18];
    const float* bbo     = (const float*)d_in[19];
    const float* bln2g   = (const float*)d_in[20];
    const float* bln2b   = (const float*)d_in[21];
    const float* fcW     = (const float*)d_in[22];
    const float* fcb     = (const float*)d_in[23];
    const int*   tran_idx= (const int*)d_in[24];
    const int*   tran_len= (const int*)d_in[25];
    const int*   span_idx= (const int*)d_in[26];

    float* buf = nullptr;
    cudaGetSymbolAddress((void**)&buf, d_buf);

    float* tmps = buf + O_TMPS;
    float* xpf  = buf + O_XPF;
    float* xpb  = buf + O_XPB;
    float* xbuf = buf + O_X;
    float* hout = buf + O_HOUT;
    float* outs = buf + O_OUTS;
    float* outg = buf + O_OUTG;
    float* qkv  = buf + O_QKV;
    float* sc   = buf + O_SC;
    float* ctx  = buf + O_CTX;
    float* p1   = buf + O_P1;
    float* abuf = buf + O_A;
    float* hbuf = buf + O_H;
    float* adjb = buf + O_ADJ;
    float* den  = buf + O_DEN;
    float* ybuf = buf + O_Y;

    // 1. segment sums
    tmps_kernel<<<NTOK, 256>>>(bert, tran_idx, tmps);

    // 2. LSTM input projections
    gemm(tmps, EMB, 0, Wih_f, 4*HH, 0, b_f, xpf, 4*HH, 0, NTOK, 4*HH, EMB, 1.f, 0, 1);
    gemm(tmps, EMB, 0, Wih_b, 4*HH, 0, b_b, xpb, 4*HH, 0, NTOK, 4*HH, EMB, 1.f, 0, 1);

    // 3. recurrence (writes x, outs, outg, hout)
    lstm_kernel<<<2*BB, 400>>>(xpf, xpb, Whh_f, Whh_b, tran_len, xbuf, outs, outg, hout);

    // 4. adjacency prep (fused clamp + denom)
    adjden_kernel<<<NTOK, 256>>>(adj1, adj2, adjb, den);

    const float inv_sqrt_d = 0.07071067811865475f;   // 1/sqrt(200)

    for (int i = 0; i < KLAY; i++) {
        const float* Wqkv = bWqkv + (long long)i*DD*3*DD;
        const float* bqkv = bbqkv + (long long)i*3*DD;
        const float* Wao  = bWao  + (long long)i*DD*DD;
        const float* bao  = bbao  + (long long)i*DD;
        const float* g1   = bln1g + (long long)i*DD;
        const float* b1   = bln1b + (long long)i*DD;
        const float* Wi   = bWi   + (long long)i*DD*DD;
        const float* bi   = bbi   + (long long)i*DD;
        const float* Wo   = bWo   + (long long)i*DD*DD;
        const float* bo   = bbo   + (long long)i*DD;
        const float* g2   = bln2g + (long long)i*DD;
        const float* b2   = bln2b + (long long)i*DD;

        // attention branch
        gemm(outs, DD, 0, Wqkv, 3*DD, 0, bqkv, qkv, 3*DD, 0, NTOK, 3*DD, DD, 1.f, 0, 1);
        gemm(qkv,       3*DD, (long long)MAXL*3*DD,
             qkv + DD,  3*DD, (long long)MAXL*3*DD,
             nullptr, sc, MAXL, (long long)MAXL*MAXL,
             MAXL, MAXL, DD, inv_sqrt_d, 1, BB);
        softmax_kernel<<<NTOK, 256>>>(sc, tran_len);
        gemm(sc,         MAXL, (long long)MAXL*MAXL,
             qkv + 2*DD, 3*DD, (long long)MAXL*3*DD,
             nullptr, ctx, DD, (long long)MAXL*DD,
             MAXL, DD, MAXL, 1.f, 0, BB);
        gemm(ctx, DD, 0, Wao, DD, 0, bao, p1, DD, 0, NTOK, DD, DD, 1.f, 0, 1);
        ln_residual_kernel<<<NTOK, 256>>>(p1, outs, g1, b1, abuf);
        gemm(abuf, DD, 0, Wi, DD, 0, bi, hbuf, DD, 0, NTOK, DD, DD, 1.f, 0, 1, /*gelu*/1);
        gemm(hbuf, DD, 0, Wo, DD, 0, bo, p1, DD, 0, NTOK, DD, DD, 1.f, 0, 1);
        ln_residual_kernel<<<NTOK, 256>>>(p1, abuf, g2, b2, outs);

        // GCN branch: y = outg @ gcW ; outg += relu((adj @ y)/den)  (fused epilogue)
        gemm(outg, DD, 0, gcW, DD, 0, nullptr, ybuf, DD, 0, NTOK, DD, DD, 1.f, 0, 1);
        gemm(adjb, MAXL, (long long)MAXL*MAXL,
             ybuf, DD,   (long long)MAXL*DD,
             nullptr, outg, DD, (long long)MAXL*DD,
             MAXL, DD, MAXL, 1.f, 0, BB,
             /*op=gcn*/2, den, MAXL);
    }

    // 6. final features + fc
    final_kernel<<<BB, 256>>>(outs, outg, xbuf, hout, span_idx, fcW, fcb, (float*)d_out);
}